// round 5
// baseline (speedup 1.0000x reference)
#include <cuda_runtime.h>
#include <math.h>

#define NB 4
#define T 72000
#define TS 300
#define NCB 8
#define CBS 1024
#define CBD 64
#define DM 512

// out offsets (floats): a_tokens, b_logits, s1, s2, s3, s4
#define OFF_A  0
#define OFF_BL 9600
#define OFF_S1 316800
#define OFF_S2 316824
#define OFF_S3 317848
#define OFF_S4 319896

#define NPOS (NB * TS)   // 1200

__device__ float g_z[NPOS * DM];          // encoder output z
__device__ float g_cn[NCB * CBS];         // 0.5*|c|^2
__device__ float g_w2t[320 * 128];        // [(kk*64+i)][o]
__device__ float g_w3t[640 * 256];        // [(kk*128+i)][o]
__device__ float g_w4t[768 * 512];        // [(kk*256+i)][o]
__device__ float g_hwt[DM * 256];         // [d][h*64+o]
__device__ float g_cbt[NCB * CBD * CBS];  // [i][d][code]
__device__ float g_a1[NPOS * 11 * 64];    // elu(conv1) [pos][off 0..10][ch]
__device__ float g_a2[NPOS * 7 * 128];    // elu(conv2) [pos][off 0..6][ch]
__device__ float g_a3[NPOS * 3 * 256];    // elu(conv3) [pos][off 0..2][ch]

__device__ __forceinline__ float elu1(float x) { return x > 0.f ? x : expm1f(x); }

__device__ __forceinline__ unsigned fordu(float f) {
    unsigned u = __float_as_uint(f);
    return u ^ (unsigned)(((int)u >> 31) | 0x80000000);
}

// ---------------------------------------------------------------------------
// prep: tiled transposes (coalesced both ways) + code half-norms
// ---------------------------------------------------------------------------
__global__ __launch_bounds__(256) void prep_kernel(
    const float* __restrict__ w2, const float* __restrict__ w3,
    const float* __restrict__ w4, const float* __restrict__ hw,
    const float* __restrict__ cb)
{
    __shared__ float ts[32 * 33];
    const int tid = threadIdx.x;
    int bid = blockIdx.x;

    if (bid < 1224) {
        const float* src; float* dst;
        int r0, c0, SP, NO, cdiv, cmul, cin, dbase = 0;
        if (bid < 40) {                // w2: src 128x320 -> dst[(kk*64+i)][o]
            src = w2; dst = g_w2t; SP = 320; NO = 128; cdiv = 5; cmul = 64; cin = 1;
            r0 = (bid & 3) * 32; c0 = (bid >> 2) * 32;
        } else if (bid < 200) {        // w3: 256x640
            bid -= 40;
            src = w3; dst = g_w3t; SP = 640; NO = 256; cdiv = 5; cmul = 128; cin = 1;
            r0 = (bid & 7) * 32; c0 = (bid >> 3) * 32;
        } else if (bid < 584) {        // w4: 512x768
            bid -= 200;
            src = w4; dst = g_w4t; SP = 768; NO = 512; cdiv = 3; cmul = 256; cin = 1;
            r0 = (bid & 15) * 32; c0 = (bid >> 4) * 32;
        } else if (bid < 712) {        // hw: 256x512 plain transpose
            bid -= 584;
            src = hw; dst = g_hwt; SP = 512; NO = 256; cdiv = 1; cmul = 1; cin = 0;
            r0 = (bid & 7) * 32; c0 = (bid >> 3) * 32;
        } else {                       // cb: per-codebook 1024x64 plain transpose
            bid -= 712;
            int i = bid >> 6; int t = bid & 63;
            src = cb + i * 65536; dst = g_cbt; dbase = i * 65536;
            SP = 64; NO = 1024; cdiv = 1; cmul = 1; cin = 0;
            r0 = (t >> 1) * 32; c0 = (t & 1) * 32;
        }
        for (int l = tid; l < 1024; l += 256) {
            int r = l >> 5, c = l & 31;
            ts[r * 33 + c] = src[(r0 + r) * SP + c0 + c];
        }
        __syncthreads();
        for (int l = tid; l < 1024; l += 256) {
            int r = l >> 5, c = l & 31;
            int colidx = c0 + r;
            int drow;
            if (cin) drow = (colidx % cdiv) * cmul + colidx / cdiv;
            else     drow = colidx;
            dst[dbase + drow * NO + r0 + c] = ts[c * 33 + r];
        }
    } else {
        bid -= 1224;
        const int wid = tid >> 5, lane = tid & 31;
        int code0 = bid * 32 + wid * 4;
        #pragma unroll
        for (int cc = 0; cc < 4; cc++) {
            const float* p = cb + (code0 + cc) * CBD;
            float v1 = p[lane], v2 = p[lane + 32];
            float s = fmaf(v1, v1, v2 * v2);
            #pragma unroll
            for (int off = 16; off > 0; off >>= 1)
                s += __shfl_down_sync(0xFFFFFFFFu, s, off);
            if (lane == 0) g_cn[code0 + cc] = 0.5f * s;
        }
    }
}

// ---------------------------------------------------------------------------
// conv1: audio -> g_a1 [pos][11][64], elu applied. 8 positions per block.
// ---------------------------------------------------------------------------
__global__ __launch_bounds__(256) void conv1_kernel(
    const float* __restrict__ audio,
    const float* __restrict__ w1c, const float* __restrict__ b1c,
    float* __restrict__ out)
{
    __shared__ float aud[8 * 17];
    __shared__ float w1s[64 * 7];
    const int tid = threadIdx.x;
    const int pos0 = blockIdx.x * 8;

    for (int idx = tid; idx < 64 * 7; idx += 256) w1s[idx] = w1c[idx];
    for (int idx = tid; idx < 8 * 17; idx += 256) {
        int p = idx / 17, u = idx - p * 17;
        int pos = pos0 + p;
        int b = pos / TS, t = pos - b * TS;
        aud[idx] = audio[b * T + t * 240 + 223 + u];
    }
    __syncthreads();

    for (int idx = tid; idx < 8 * 11 * 64; idx += 256) {
        int ch = idx & 63;
        int r = idx >> 6;
        int j = r % 11, p = r / 11;
        float acc = b1c[ch];
        #pragma unroll
        for (int k = 0; k < 7; k++) acc = fmaf(w1s[ch * 7 + k], aud[p * 17 + j + k], acc);
        g_a1[(pos0 + p) * 704 + j * 64 + ch] = elu1(acc);
    }

    if (blockIdx.x == 0 && tid < 24) {
        int b = tid / 6, u = tid % 6;
        out[OFF_S1 + tid] = audio[b * T + (T - 6) + u];
    }
}

// ---------------------------------------------------------------------------
// GEMM-style conv: dst[m][n] = elu( sum_k src[rowbase(m)+k] * wt[k][n] + bias[n] )
// ---------------------------------------------------------------------------
template<int KDIM, int NOUT, int MROWS, int JDIV, int JMUL, int CH>
__global__ __launch_bounds__(256) void gemm_conv(
    const float* __restrict__ src, const float* __restrict__ wt,
    const float* __restrict__ bias, float* __restrict__ dst)
{
    __shared__ float actS[32 * 36];
    const int tid = threadIdx.x;
    const int o = tid & 127;
    const int mh = tid >> 7;
    const int n0 = blockIdx.y * 128;
    const int m0 = blockIdx.x * 32;

    float acc[16];
    #pragma unroll
    for (int i = 0; i < 16; i++) acc[i] = 0.f;

    const int lr = tid >> 3;
    const int lc4 = tid & 7;
    int lbase = -1;
    {
        int m = m0 + lr;
        if (m < MROWS) lbase = (m / JDIV) * JMUL + (m % JDIV) * CH;
    }

    for (int kc0 = 0; kc0 < KDIM; kc0 += 32) {
        float4 v = make_float4(0.f, 0.f, 0.f, 0.f);
        if (lbase >= 0) v = *(const float4*)(src + lbase + kc0 + lc4 * 4);
        actS[(lc4 * 4 + 0) * 36 + lr] = v.x;
        actS[(lc4 * 4 + 1) * 36 + lr] = v.y;
        actS[(lc4 * 4 + 2) * 36 + lr] = v.z;
        actS[(lc4 * 4 + 3) * 36 + lr] = v.w;
        __syncthreads();

        #pragma unroll
        for (int h2 = 0; h2 < 2; h2++) {
            float wr[16];
            #pragma unroll
            for (int kk = 0; kk < 16; kk++)
                wr[kk] = wt[(kc0 + h2 * 16 + kk) * NOUT + n0 + o];
            #pragma unroll
            for (int kk = 0; kk < 16; kk++) {
                const float* ap = actS + (h2 * 16 + kk) * 36 + mh * 16;
                float4 a0 = *(const float4*)(ap + 0);
                float4 a1 = *(const float4*)(ap + 4);
                float4 a2 = *(const float4*)(ap + 8);
                float4 a3 = *(const float4*)(ap + 12);
                float w = wr[kk];
                acc[0]  = fmaf(w, a0.x, acc[0]);  acc[1]  = fmaf(w, a0.y, acc[1]);
                acc[2]  = fmaf(w, a0.z, acc[2]);  acc[3]  = fmaf(w, a0.w, acc[3]);
                acc[4]  = fmaf(w, a1.x, acc[4]);  acc[5]  = fmaf(w, a1.y, acc[5]);
                acc[6]  = fmaf(w, a1.z, acc[6]);  acc[7]  = fmaf(w, a1.w, acc[7]);
                acc[8]  = fmaf(w, a2.x, acc[8]);  acc[9]  = fmaf(w, a2.y, acc[9]);
                acc[10] = fmaf(w, a2.z, acc[10]); acc[11] = fmaf(w, a2.w, acc[11]);
                acc[12] = fmaf(w, a3.x, acc[12]); acc[13] = fmaf(w, a3.y, acc[13]);
                acc[14] = fmaf(w, a3.z, acc[14]); acc[15] = fmaf(w, a3.w, acc[15]);
            }
        }
        __syncthreads();
    }

    float bb = bias[n0 + o];
    #pragma unroll
    for (int mm = 0; mm < 16; mm++) {
        int m = m0 + mh * 16 + mm;
        if (m < MROWS) dst[m * NOUT + n0 + o] = elu1(acc[mm] + bb);
    }
}

// ---------------------------------------------------------------------------
// tail: s2/s3/s4 from act buffers (last position per batch)
// per-batch budget: 256 (s2) + 512 (s3) + 512 (s4) = 1280   [FIX: was 1536]
// ---------------------------------------------------------------------------
__global__ void tail_kernel(float* __restrict__ out) {
    int idx = blockIdx.x * blockDim.x + threadIdx.x;
    if (idx >= 4 * 1280) return;
    int b = idx / 1280;
    int r = idx - b * 1280;
    int pos = b * TS + (TS - 1);
    if (r < 256) {
        int c = r >> 2, u = r & 3;
        out[OFF_S2 + (b * 64 + c) * 4 + u] = g_a1[pos * 704 + (7 + u) * 64 + c];
    } else if (r < 768) {
        int rr = r - 256;
        int c = rr >> 2, u = rr & 3;
        out[OFF_S3 + (b * 128 + c) * 4 + u] = g_a2[pos * 896 + (3 + u) * 128 + c];
    } else {
        int rr = r - 768;                   // rr in [0,512)
        int c = rr >> 1, u = rr & 1;        // c in [0,256)
        out[OFF_S4 + (b * 256 + c) * 2 + u] = g_a3[pos * 768 + (1 + u) * 256 + c];
    }
}

// ---------------------------------------------------------------------------
// rvq + head (unchanged from R2, which passed)
// ---------------------------------------------------------------------------
#define RP 10
__global__ __launch_bounds__(256) void rvq_kernel(
    const float* __restrict__ cb,
    const float* __restrict__ hb,
    float* __restrict__ out)
{
    __shared__ float zblk[RP * DM];
    __shared__ float zqsh[RP * DM];
    __shared__ float rs[RP * 64];
    __shared__ unsigned long long cand[RP * 8];
    __shared__ unsigned long long bestk[RP];

    const int tid = threadIdx.x;
    const int lane = tid & 31;
    const int wid = tid >> 5;
    const int b = blockIdx.x / 30;
    const int g = blockIdx.x % 30;

    for (int idx = tid; idx < RP * DM; idx += 256) {
        int p = idx >> 9;
        zblk[idx] = g_z[(b * TS + g * RP + p) * DM + (idx & 511)];
    }
    __syncthreads();
    for (int idx = tid; idx < RP * 64; idx += 256) {
        int p = idx >> 6;
        rs[idx] = zblk[p * DM + (idx & 63)];
    }
    __syncthreads();

    for (int i = 0; i < NCB; i++) {
        const float* cbti = g_cbt + i * CBD * CBS;
        float dot[4][RP];
        #pragma unroll
        for (int q = 0; q < 4; q++)
            #pragma unroll
            for (int p = 0; p < RP; p++) dot[q][p] = 0.f;
        for (int d = 0; d < CBD; d++) {
            float cv[4];
            #pragma unroll
            for (int q = 0; q < 4; q++) cv[q] = cbti[d * CBS + tid + q * 256];
            #pragma unroll
            for (int p = 0; p < RP; p++) {
                float rv = rs[p * 64 + d];
                #pragma unroll
                for (int q = 0; q < 4; q++) dot[q][p] = fmaf(cv[q], rv, dot[q][p]);
            }
        }
        unsigned long long best[RP];
        #pragma unroll
        for (int p = 0; p < RP; p++) best[p] = 0ull;
        #pragma unroll
        for (int q = 0; q < 4; q++) {
            int code = tid + q * 256;
            float cn = g_cn[i * CBS + code];
            unsigned invc = ~(unsigned)code;
            #pragma unroll
            for (int p = 0; p < RP; p++) {
                float sc = dot[q][p] - cn;
                unsigned long long key = (((unsigned long long)fordu(sc)) << 32) | invc;
                if (key > best[p]) best[p] = key;
            }
        }
        #pragma unroll
        for (int off = 16; off > 0; off >>= 1) {
            #pragma unroll
            for (int p = 0; p < RP; p++) {
                unsigned long long other = __shfl_down_sync(0xFFFFFFFFu, best[p], off);
                if (other > best[p]) best[p] = other;
            }
        }
        if (lane == 0) {
            #pragma unroll
            for (int p = 0; p < RP; p++) cand[p * 8 + wid] = best[p];
        }
        __syncthreads();
        if (tid < RP) {
            unsigned long long m = cand[tid * 8];
            #pragma unroll
            for (int w = 1; w < 8; w++) {
                unsigned long long v = cand[tid * 8 + w];
                if (v > m) m = v;
            }
            bestk[tid] = m;
            unsigned code = ~(unsigned)(m & 0xFFFFFFFFull);
            out[OFF_A + (b * NCB + i) * TS + g * RP + tid] = (float)code;
        }
        __syncthreads();
        for (int idx = tid; idx < RP * 64; idx += 256) {
            int p = idx >> 6, d = idx & 63;
            unsigned code = ~(unsigned)(bestk[p] & 0xFFFFFFFFull);
            float qv = cb[(i * CBS + code) * CBD + d];
            zqsh[p * DM + i * 64 + d] = qv;
            if (i < NCB - 1)
                rs[idx] = zblk[p * DM + (i + 1) * 64 + d] + rs[idx] - qv;
        }
        __syncthreads();
    }

    {
        float acc[RP];
        #pragma unroll
        for (int p = 0; p < RP; p++) acc[p] = 0.f;
        for (int d = 0; d < DM; d++) {
            float wv = g_hwt[d * 256 + tid];
            #pragma unroll
            for (int p = 0; p < RP; p++) acc[p] = fmaf(wv, zqsh[p * DM + d], acc[p]);
        }
        int h = tid >> 6, o = tid & 63;
        float bb = hb[tid];
        #pragma unroll
        for (int p = 0; p < RP; p++)
            out[OFF_BL + ((b * 4 + h) * TS + g * RP + p) * 64 + o] = acc[p] + bb;
    }
}

// ---------------------------------------------------------------------------
extern "C" void kernel_launch(void* const* d_in, const int* in_sizes, int n_in,
                              void* d_out, int out_size)
{
    const float* audio = (const float*)d_in[0];
    const float* w1 = (const float*)d_in[1];
    const float* b1 = (const float*)d_in[2];
    const float* w2 = (const float*)d_in[3];
    const float* b2 = (const float*)d_in[4];
    const float* w3 = (const float*)d_in[5];
    const float* b3 = (const float*)d_in[6];
    const float* w4 = (const float*)d_in[7];
    const float* b4 = (const float*)d_in[8];
    const float* cb = (const float*)d_in[9];
    const float* hw = (const float*)d_in[10];
    const float* hb = (const float*)d_in[11];
    float* out = (float*)d_out;

    prep_kernel<<<1480, 256>>>(w2, w3, w4, hw, cb);
    conv1_kernel<<<150, 256>>>(audio, w1, b1, out);

    float* g_a1p; cudaGetSymbolAddress((void**)&g_a1p, g_a1);
    float* g_a2p; cudaGetSymbolAddress((void**)&g_a2p, g_a2);
    float* g_a3p; cudaGetSymbolAddress((void**)&g_a3p, g_a3);
    float* g_zp;  cudaGetSymbolAddress((void**)&g_zp, g_z);
    float* g_w2tp; cudaGetSymbolAddress((void**)&g_w2tp, g_w2t);
    float* g_w3tp; cudaGetSymbolAddress((void**)&g_w3tp, g_w3t);
    float* g_w4tp; cudaGetSymbolAddress((void**)&g_w4tp, g_w4t);

    gemm_conv<320, 128, 8400, 7, 704, 64><<<dim3(263, 1), 256>>>(g_a1p, g_w2tp, b2, g_a2p);
    gemm_conv<640, 256, 3600, 3, 896, 128><<<dim3(113, 2), 256>>>(g_a2p, g_w3tp, b3, g_a3p);
    gemm_conv<768, 512, 1200, 1, 768, 0><<<dim3(38, 4), 256>>>(g_a3p, g_w4tp, b4, g_zp);

    tail_kernel<<<20, 256>>>(out);
    rvq_kernel<<<120, 256>>>(cb, hb, out);
}

// round 6
// speedup vs baseline: 1.0360x; 1.0360x over previous
#include <cuda_runtime.h>
#include <math.h>

#define NB 4
#define T 72000
#define TS 300
#define NCB 8
#define CBS 1024
#define CBD 64
#define DM 512

// out offsets (floats): a_tokens, b_logits, s1, s2, s3, s4
#define OFF_A  0
#define OFF_BL 9600
#define OFF_S1 316800
#define OFF_S2 316824
#define OFF_S3 317848
#define OFF_S4 319896

#define NPOS (NB * TS)   // 1200

__device__ float g_z[NPOS * DM];          // encoder output z
__device__ float g_cn[NCB * CBS];         // 0.5*|c|^2
__device__ float g_w2t[320 * 128];        // [(kk*64+i)][o]
__device__ float g_w3t[640 * 256];        // [(kk*128+i)][o]
__device__ float g_w4t[768 * 512];        // [(kk*256+i)][o]
__device__ float g_hwt[DM * 256];         // [d][h*64+o]
__device__ float g_cbt[NCB * CBD * CBS];  // [i][d][code]
__device__ float g_a1[NPOS * 11 * 64];    // elu(conv1) [pos][off 0..10][ch]
__device__ float g_a2[NPOS * 7 * 128];    // elu(conv2) [pos][off 0..6][ch]
__device__ float g_a3[NPOS * 3 * 256];    // elu(conv3) [pos][off 0..2][ch]

__device__ __forceinline__ float elu1(float x) { return x > 0.f ? x : expm1f(x); }

__device__ __forceinline__ unsigned fordu(float f) {
    unsigned u = __float_as_uint(f);
    return u ^ (unsigned)(((int)u >> 31) | 0x80000000);
}

// packed f32x2 helpers (sm_103a 2x fp32; PTX-only, ptxas never emits FFMA2)
__device__ __forceinline__ unsigned long long pack2(float lo, float hi) {
    unsigned long long r;
    asm("mov.b64 %0, {%1, %2};" : "=l"(r) : "f"(lo), "f"(hi));
    return r;
}
__device__ __forceinline__ void fma2(unsigned long long& d,
                                     unsigned long long a, unsigned long long b) {
    asm("fma.rn.f32x2 %0, %1, %2, %0;" : "+l"(d) : "l"(a), "l"(b));
}
__device__ __forceinline__ float lo32(unsigned long long v) {
    return __uint_as_float((unsigned)v);
}
__device__ __forceinline__ float hi32(unsigned long long v) {
    return __uint_as_float((unsigned)(v >> 32));
}

// ---------------------------------------------------------------------------
// prep: tiled transposes (coalesced both ways) + code half-norms
// ---------------------------------------------------------------------------
__global__ __launch_bounds__(256) void prep_kernel(
    const float* __restrict__ w2, const float* __restrict__ w3,
    const float* __restrict__ w4, const float* __restrict__ hw,
    const float* __restrict__ cb)
{
    __shared__ float ts[32 * 33];
    const int tid = threadIdx.x;
    int bid = blockIdx.x;

    if (bid < 1224) {
        const float* src; float* dst;
        int r0, c0, SP, NO, cdiv, cmul, cin, dbase = 0;
        if (bid < 40) {                // w2: src 128x320 -> dst[(kk*64+i)][o]
            src = w2; dst = g_w2t; SP = 320; NO = 128; cdiv = 5; cmul = 64; cin = 1;
            r0 = (bid & 3) * 32; c0 = (bid >> 2) * 32;
        } else if (bid < 200) {        // w3: 256x640
            bid -= 40;
            src = w3; dst = g_w3t; SP = 640; NO = 256; cdiv = 5; cmul = 128; cin = 1;
            r0 = (bid & 7) * 32; c0 = (bid >> 3) * 32;
        } else if (bid < 584) {        // w4: 512x768
            bid -= 200;
            src = w4; dst = g_w4t; SP = 768; NO = 512; cdiv = 3; cmul = 256; cin = 1;
            r0 = (bid & 15) * 32; c0 = (bid >> 4) * 32;
        } else if (bid < 712) {        // hw: 256x512 plain transpose
            bid -= 584;
            src = hw; dst = g_hwt; SP = 512; NO = 256; cdiv = 1; cmul = 1; cin = 0;
            r0 = (bid & 7) * 32; c0 = (bid >> 3) * 32;
        } else {                       // cb: per-codebook 1024x64 plain transpose
            bid -= 712;
            int i = bid >> 6; int t = bid & 63;
            src = cb + i * 65536; dst = g_cbt; dbase = i * 65536;
            SP = 64; NO = 1024; cdiv = 1; cmul = 1; cin = 0;
            r0 = (t >> 1) * 32; c0 = (t & 1) * 32;
        }
        for (int l = tid; l < 1024; l += 256) {
            int r = l >> 5, c = l & 31;
            ts[r * 33 + c] = src[(r0 + r) * SP + c0 + c];
        }
        __syncthreads();
        for (int l = tid; l < 1024; l += 256) {
            int r = l >> 5, c = l & 31;
            int colidx = c0 + r;
            int drow;
            if (cin) drow = (colidx % cdiv) * cmul + colidx / cdiv;
            else     drow = colidx;
            dst[dbase + drow * NO + r0 + c] = ts[c * 33 + r];
        }
    } else {
        bid -= 1224;
        const int wid = tid >> 5, lane = tid & 31;
        int code0 = bid * 32 + wid * 4;
        #pragma unroll
        for (int cc = 0; cc < 4; cc++) {
            const float* p = cb + (code0 + cc) * CBD;
            float v1 = p[lane], v2 = p[lane + 32];
            float s = fmaf(v1, v1, v2 * v2);
            #pragma unroll
            for (int off = 16; off > 0; off >>= 1)
                s += __shfl_down_sync(0xFFFFFFFFu, s, off);
            if (lane == 0) g_cn[code0 + cc] = 0.5f * s;
        }
    }
}

// ---------------------------------------------------------------------------
// conv1: audio -> g_a1 [pos][11][64], elu applied. 8 positions per block.
// ---------------------------------------------------------------------------
__global__ __launch_bounds__(256) void conv1_kernel(
    const float* __restrict__ audio,
    const float* __restrict__ w1c, const float* __restrict__ b1c,
    float* __restrict__ out)
{
    __shared__ float aud[8 * 17];
    __shared__ float w1s[64 * 7];
    const int tid = threadIdx.x;
    const int pos0 = blockIdx.x * 8;

    for (int idx = tid; idx < 64 * 7; idx += 256) w1s[idx] = w1c[idx];
    for (int idx = tid; idx < 8 * 17; idx += 256) {
        int p = idx / 17, u = idx - p * 17;
        int pos = pos0 + p;
        int b = pos / TS, t = pos - b * TS;
        aud[idx] = audio[b * T + t * 240 + 223 + u];
    }
    __syncthreads();

    for (int idx = tid; idx < 8 * 11 * 64; idx += 256) {
        int ch = idx & 63;
        int r = idx >> 6;
        int j = r % 11, p = r / 11;
        float acc = b1c[ch];
        #pragma unroll
        for (int k = 0; k < 7; k++) acc = fmaf(w1s[ch * 7 + k], aud[p * 17 + j + k], acc);
        g_a1[(pos0 + p) * 704 + j * 64 + ch] = elu1(acc);
    }

    if (blockIdx.x == 0 && tid < 24) {
        int b = tid / 6, u = tid % 6;
        out[OFF_S1 + tid] = audio[b * T + (T - 6) + u];
    }
}

// ---------------------------------------------------------------------------
// GEMM-style conv with double-buffered act staging + packed f32x2 FMAs.
// dst[m][n] = elu( sum_k src[rowbase(m)+k] * wt[k][n] + bias[n] )
// BM=32, BN=128, KC=32, 256 threads. Acc pairs across adjacent M rows.
// ---------------------------------------------------------------------------
template<int KDIM, int NOUT, int MROWS, int JDIV, int JMUL, int CH>
__global__ __launch_bounds__(256) void gemm_conv(
    const float* __restrict__ src, const float* __restrict__ wt,
    const float* __restrict__ bias, float* __restrict__ dst)
{
    __shared__ float actS[2][32 * 36];   // [buf][k][row], pitch 36
    const int tid = threadIdx.x;
    const int o = tid & 127;
    const int mh = tid >> 7;
    const int n0 = blockIdx.y * 128;
    const int m0 = blockIdx.x * 32;

    unsigned long long acc2[8];
    #pragma unroll
    for (int i = 0; i < 8; i++) acc2[i] = 0ull;

    const int lr = tid >> 3;
    const int lc4 = tid & 7;
    const float* sp = 0;
    {
        int m = m0 + lr;
        if (m < MROWS) sp = src + (m / JDIV) * JMUL + (m % JDIV) * CH;
    }

    // prologue: stage chunk 0 into buffer 0
    {
        float4 v = make_float4(0.f, 0.f, 0.f, 0.f);
        if (sp) v = *(const float4*)(sp + lc4 * 4);
        float* as = actS[0];
        as[(lc4 * 4 + 0) * 36 + lr] = v.x;
        as[(lc4 * 4 + 1) * 36 + lr] = v.y;
        as[(lc4 * 4 + 2) * 36 + lr] = v.z;
        as[(lc4 * 4 + 3) * 36 + lr] = v.w;
    }
    __syncthreads();

    int buf = 0;
    for (int kc0 = 0; kc0 < KDIM; kc0 += 32) {
        // prefetch next chunk into regs
        float4 nv = make_float4(0.f, 0.f, 0.f, 0.f);
        const bool have_next = (kc0 + 32 < KDIM);
        if (have_next && sp) nv = *(const float4*)(sp + kc0 + 32 + lc4 * 4);

        const float* as = actS[buf];
        #pragma unroll
        for (int h2 = 0; h2 < 2; h2++) {
            float wr[16];
            #pragma unroll
            for (int kk = 0; kk < 16; kk++)
                wr[kk] = wt[(kc0 + h2 * 16 + kk) * NOUT + n0 + o];
            #pragma unroll
            for (int kk = 0; kk < 16; kk++) {
                unsigned long long wp = pack2(wr[kk], wr[kk]);
                const ulonglong2* ap =
                    (const ulonglong2*)(as + (h2 * 16 + kk) * 36 + mh * 16);
                ulonglong2 a01 = ap[0];
                ulonglong2 a23 = ap[1];
                ulonglong2 a45 = ap[2];
                ulonglong2 a67 = ap[3];
                fma2(acc2[0], wp, a01.x); fma2(acc2[1], wp, a01.y);
                fma2(acc2[2], wp, a23.x); fma2(acc2[3], wp, a23.y);
                fma2(acc2[4], wp, a45.x); fma2(acc2[5], wp, a45.y);
                fma2(acc2[6], wp, a67.x); fma2(acc2[7], wp, a67.y);
            }
        }

        if (have_next) {
            float* ns = actS[buf ^ 1];
            ns[(lc4 * 4 + 0) * 36 + lr] = nv.x;
            ns[(lc4 * 4 + 1) * 36 + lr] = nv.y;
            ns[(lc4 * 4 + 2) * 36 + lr] = nv.z;
            ns[(lc4 * 4 + 3) * 36 + lr] = nv.w;
        }
        __syncthreads();
        buf ^= 1;
    }

    float bb = bias[n0 + o];
    #pragma unroll
    for (int i = 0; i < 8; i++) {
        int mA = m0 + mh * 16 + 2 * i;
        int mB = mA + 1;
        if (mA < MROWS) dst[mA * NOUT + n0 + o] = elu1(lo32(acc2[i]) + bb);
        if (mB < MROWS) dst[mB * NOUT + n0 + o] = elu1(hi32(acc2[i]) + bb);
    }
}

// ---------------------------------------------------------------------------
// tail: s2/s3/s4 (last position per batch). budget 256+512+512 = 1280/batch
// ---------------------------------------------------------------------------
__global__ void tail_kernel(float* __restrict__ out) {
    int idx = blockIdx.x * blockDim.x + threadIdx.x;
    if (idx >= 4 * 1280) return;
    int b = idx / 1280;
    int r = idx - b * 1280;
    int pos = b * TS + (TS - 1);
    if (r < 256) {
        int c = r >> 2, u = r & 3;
        out[OFF_S2 + (b * 64 + c) * 4 + u] = g_a1[pos * 704 + (7 + u) * 64 + c];
    } else if (r < 768) {
        int rr = r - 256;
        int c = rr >> 2, u = rr & 3;
        out[OFF_S3 + (b * 128 + c) * 4 + u] = g_a2[pos * 896 + (3 + u) * 128 + c];
    } else {
        int rr = r - 768;
        int c = rr >> 1, u = rr & 1;
        out[OFF_S4 + (b * 256 + c) * 2 + u] = g_a3[pos * 768 + (1 + u) * 256 + c];
    }
}

// ---------------------------------------------------------------------------
// rvq + head, with position-paired f32x2 accumulation.
// rs2/zq2 store position pairs: pair ph holds positions (2ph, 2ph+1).
// ---------------------------------------------------------------------------
#define RP 10
#define PH 5
__global__ __launch_bounds__(256) void rvq_kernel(
    const float* __restrict__ cb,
    const float* __restrict__ hb,
    float* __restrict__ out)
{
    __shared__ float zblk[RP * DM];                 // [p][d]
    __shared__ float2 zq2[DM * PH];                 // [dm][ph]
    __shared__ float2 rs2[CBD * PH];                // [d][ph]
    __shared__ unsigned long long cand[RP * 8];
    __shared__ unsigned long long bestk[RP];

    const int tid = threadIdx.x;
    const int lane = tid & 31;
    const int wid = tid >> 5;
    const int b = blockIdx.x / 30;
    const int g = blockIdx.x % 30;

    for (int idx = tid; idx < RP * DM; idx += 256) {
        int p = idx >> 9;
        zblk[idx] = g_z[(b * TS + g * RP + p) * DM + (idx & 511)];
    }
    __syncthreads();
    for (int idx = tid; idx < CBD * PH; idx += 256) {
        int d = idx / PH, ph = idx - d * PH;
        rs2[idx] = make_float2(zblk[(2 * ph) * DM + d], zblk[(2 * ph + 1) * DM + d]);
    }
    __syncthreads();

    const unsigned long long* rsu = (const unsigned long long*)rs2;

    for (int i = 0; i < NCB; i++) {
        const float* cbti = g_cbt + i * CBD * CBS;
        unsigned long long dot2[4][PH];
        #pragma unroll
        for (int q = 0; q < 4; q++)
            #pragma unroll
            for (int ph = 0; ph < PH; ph++) dot2[q][ph] = 0ull;

        for (int d = 0; d < CBD; d++) {
            unsigned long long cp[4];
            #pragma unroll
            for (int q = 0; q < 4; q++) {
                float cv = cbti[d * CBS + tid + q * 256];
                cp[q] = pack2(cv, cv);
            }
            unsigned long long rv[PH];
            #pragma unroll
            for (int ph = 0; ph < PH; ph++) rv[ph] = rsu[d * PH + ph];
            #pragma unroll
            for (int q = 0; q < 4; q++)
                #pragma unroll
                for (int ph = 0; ph < PH; ph++)
                    fma2(dot2[q][ph], cp[q], rv[ph]);
        }

        // argmax(dot - 0.5|c|^2) == argmin(dist); key packs (score, ~code)
        unsigned long long best[RP];
        #pragma unroll
        for (int p = 0; p < RP; p++) best[p] = 0ull;
        #pragma unroll
        for (int q = 0; q < 4; q++) {
            int code = tid + q * 256;
            float cn = g_cn[i * CBS + code];
            unsigned invc = ~(unsigned)code;
            #pragma unroll
            for (int ph = 0; ph < PH; ph++) {
                float sc0 = lo32(dot2[q][ph]) - cn;
                float sc1 = hi32(dot2[q][ph]) - cn;
                unsigned long long k0 = (((unsigned long long)fordu(sc0)) << 32) | invc;
                unsigned long long k1 = (((unsigned long long)fordu(sc1)) << 32) | invc;
                if (k0 > best[2 * ph])     best[2 * ph] = k0;
                if (k1 > best[2 * ph + 1]) best[2 * ph + 1] = k1;
            }
        }
        #pragma unroll
        for (int off = 16; off > 0; off >>= 1) {
            #pragma unroll
            for (int p = 0; p < RP; p++) {
                unsigned long long other = __shfl_down_sync(0xFFFFFFFFu, best[p], off);
                if (other > best[p]) best[p] = other;
            }
        }
        if (lane == 0) {
            #pragma unroll
            for (int p = 0; p < RP; p++) cand[p * 8 + wid] = best[p];
        }
        __syncthreads();
        if (tid < RP) {
            unsigned long long m = cand[tid * 8];
            #pragma unroll
            for (int w = 1; w < 8; w++) {
                unsigned long long v = cand[tid * 8 + w];
                if (v > m) m = v;
            }
            bestk[tid] = m;
            unsigned code = ~(unsigned)(m & 0xFFFFFFFFull);
            out[OFF_A + (b * NCB + i) * TS + g * RP + tid] = (float)code;
        }
        __syncthreads();
        // q into zq2 (paired), residual r = z[i+1] + (r - q)
        for (int idx = tid; idx < CBD * PH; idx += 256) {
            int d = idx / PH, ph = idx - d * PH;
            int p0 = 2 * ph, p1 = p0 + 1;
            unsigned c0 = ~(unsigned)(bestk[p0] & 0xFFFFFFFFull);
            unsigned c1 = ~(unsigned)(bestk[p1] & 0xFFFFFFFFull);
            float q0 = cb[(i * CBS + c0) * CBD + d];
            float q1 = cb[(i * CBS + c1) * CBD + d];
            zq2[(i * 64 + d) * PH + ph] = make_float2(q0, q1);
            if (i < NCB - 1) {
                float2 r = rs2[idx];
                rs2[idx] = make_float2(
                    zblk[p0 * DM + (i + 1) * 64 + d] + r.x - q0,
                    zblk[p1 * DM + (i + 1) * 64 + d] + r.y - q1);
            }
        }
        __syncthreads();
    }

    // head: b_logits[b,h,t,o] = z_q . head_w[h,o,:] + head_b[h,o]
    {
        unsigned long long acc2[PH];
        #pragma unroll
        for (int ph = 0; ph < PH; ph++) acc2[ph] = 0ull;
        const unsigned long long* zqu = (const unsigned long long*)zq2;
        for (int dm = 0; dm < DM; dm++) {
            float w = g_hwt[dm * 256 + tid];
            unsigned long long wp = pack2(w, w);
            #pragma unroll
            for (int ph = 0; ph < PH; ph++)
                fma2(acc2[ph], wp, zqu[dm * PH + ph]);
        }
        int h = tid >> 6, o = tid & 63;
        float bb = hb[tid];
        #pragma unroll
        for (int ph = 0; ph < PH; ph++) {
            int p0 = 2 * ph, p1 = p0 + 1;
            out[OFF_BL + ((b * 4 + h) * TS + g * RP + p0) * 64 + o] = lo32(acc2[ph]) + bb;
            out[OFF_BL + ((b * 4 + h) * TS + g * RP + p1) * 64 + o] = hi32(acc2[ph]) + bb;
        }
    }
}

// ---------------------------------------------------------------------------
extern "C" void kernel_launch(void* const* d_in, const int* in_sizes, int n_in,
                              void* d_out, int out_size)
{
    const float* audio = (const float*)d_in[0];
    const float* w1 = (const float*)d_in[1];
    const float* b1 = (const float*)d_in[2];
    const float* w2 = (const float*)d_in[3];
    const float* b2 = (const float*)d_in[4];
    const float* w3 = (const float*)d_in[5];
    const float* b3 = (const float*)d_in[6];
    const float* w4 = (const float*)d_in[7];
    const float* b4 = (const float*)d_in[8];
    const float* cb = (const float*)d_in[9];
    const float* hw = (const float*)d_in[10];
    const float* hb = (const float*)d_in[11];
    float* out = (float*)d_out;

    prep_kernel<<<1480, 256>>>(w2, w3, w4, hw, cb);
    conv1_kernel<<<150, 256>>>(audio, w1, b1, out);

    float* g_a1p; cudaGetSymbolAddress((void**)&g_a1p, g_a1);
    float* g_a2p; cudaGetSymbolAddress((void**)&g_a2p, g_a2);
    float* g_a3p; cudaGetSymbolAddress((void**)&g_a3p, g_a3);
    float* g_zp;  cudaGetSymbolAddress((void**)&g_zp, g_z);
    float* g_w2tp; cudaGetSymbolAddress((void**)&g_w2tp, g_w2t);
    float* g_w3tp; cudaGetSymbolAddress((void**)&g_w3tp, g_w3t);
    float* g_w4tp; cudaGetSymbolAddress((void**)&g_w4tp, g_w4t);

    gemm_conv<320, 128, 8400, 7, 704, 64><<<dim3(263, 1), 256>>>(g_a1p, g_w2tp, b2, g_a2p);
    gemm_conv<640, 256, 3600, 3, 896, 128><<<dim3(113, 2), 256>>>(g_a2p, g_w3tp, b3, g_a3p);
    gemm_conv<768, 512, 1200, 1, 768, 0><<<dim3(38, 4), 256>>>(g_a3p, g_w4tp, b4, g_zp);

    tail_kernel<<<20, 256>>>(out);
    rvq_kernel<<<120, 256>>>(cb, hb, out);
}

// round 7
// speedup vs baseline: 1.1017x; 1.0635x over previous
#include <cuda_runtime.h>
#include <math.h>

#define NB 4
#define T 72000
#define TS 300
#define NCB 8
#define CBS 1024
#define CBD 64
#define DM 512

// out offsets (floats): a_tokens, b_logits, s1, s2, s3, s4
#define OFF_A  0
#define OFF_BL 9600
#define OFF_S1 316800
#define OFF_S2 316824
#define OFF_S3 317848
#define OFF_S4 319896

#define NPOS (NB * TS)   // 1200

__device__ float g_z[NPOS * DM];          // encoder output z
__device__ float g_cn[NCB * CBS];         // 0.5*|c|^2
__device__ float g_w2t[320 * 128];        // [(kk*64+i)][o]
__device__ float g_w3t[640 * 256];        // [(kk*128+i)][o]
__device__ float g_w4t[768 * 512];        // [(kk*256+i)][o]
__device__ float g_hwt[DM * 256];         // [d][h*64+o]
__device__ float g_cbt[NCB * CBD * CBS];  // [i][d][code]
__device__ float g_a1[NPOS * 11 * 64];    // elu(conv1) [pos][off 0..10][ch]
__device__ float g_a2[NPOS * 7 * 128];    // elu(conv2) [pos][off 0..6][ch]
__device__ float g_a3[NPOS * 3 * 256];    // elu(conv3) [pos][off 0..2][ch]

__device__ __forceinline__ float elu1(float x) { return x > 0.f ? x : expm1f(x); }

__device__ __forceinline__ unsigned fordu(float f) {
    unsigned u = __float_as_uint(f);
    return u ^ (unsigned)(((int)u >> 31) | 0x80000000);
}

// packed f32x2 helpers (kept for rvq dot phase)
__device__ __forceinline__ unsigned long long pack2(float lo, float hi) {
    unsigned long long r;
    asm("mov.b64 %0, {%1, %2};" : "=l"(r) : "f"(lo), "f"(hi));
    return r;
}
__device__ __forceinline__ void fma2(unsigned long long& d,
                                     unsigned long long a, unsigned long long b) {
    asm("fma.rn.f32x2 %0, %1, %2, %0;" : "+l"(d) : "l"(a), "l"(b));
}
__device__ __forceinline__ float lo32(unsigned long long v) {
    return __uint_as_float((unsigned)v);
}
__device__ __forceinline__ float hi32(unsigned long long v) {
    return __uint_as_float((unsigned)(v >> 32));
}

// ---------------------------------------------------------------------------
// prep: tiled transposes (coalesced both ways) + code half-norms
// ---------------------------------------------------------------------------
__global__ __launch_bounds__(256) void prep_kernel(
    const float* __restrict__ w2, const float* __restrict__ w3,
    const float* __restrict__ w4, const float* __restrict__ hw,
    const float* __restrict__ cb)
{
    __shared__ float ts[32 * 33];
    const int tid = threadIdx.x;
    int bid = blockIdx.x;

    if (bid < 1224) {
        const float* src; float* dst;
        int r0, c0, SP, NO, cdiv, cmul, cin, dbase = 0;
        if (bid < 40) {                // w2: src 128x320 -> dst[(kk*64+i)][o]
            src = w2; dst = g_w2t; SP = 320; NO = 128; cdiv = 5; cmul = 64; cin = 1;
            r0 = (bid & 3) * 32; c0 = (bid >> 2) * 32;
        } else if (bid < 200) {        // w3: 256x640
            bid -= 40;
            src = w3; dst = g_w3t; SP = 640; NO = 256; cdiv = 5; cmul = 128; cin = 1;
            r0 = (bid & 7) * 32; c0 = (bid >> 3) * 32;
        } else if (bid < 584) {        // w4: 512x768
            bid -= 200;
            src = w4; dst = g_w4t; SP = 768; NO = 512; cdiv = 3; cmul = 256; cin = 1;
            r0 = (bid & 15) * 32; c0 = (bid >> 4) * 32;
        } else if (bid < 712) {        // hw: 256x512 plain transpose
            bid -= 584;
            src = hw; dst = g_hwt; SP = 512; NO = 256; cdiv = 1; cmul = 1; cin = 0;
            r0 = (bid & 7) * 32; c0 = (bid >> 3) * 32;
        } else {                       // cb: per-codebook 1024x64 plain transpose
            bid -= 712;
            int i = bid >> 6; int t = bid & 63;
            src = cb + i * 65536; dst = g_cbt; dbase = i * 65536;
            SP = 64; NO = 1024; cdiv = 1; cmul = 1; cin = 0;
            r0 = (t >> 1) * 32; c0 = (t & 1) * 32;
        }
        for (int l = tid; l < 1024; l += 256) {
            int r = l >> 5, c = l & 31;
            ts[r * 33 + c] = src[(r0 + r) * SP + c0 + c];
        }
        __syncthreads();
        for (int l = tid; l < 1024; l += 256) {
            int r = l >> 5, c = l & 31;
            int colidx = c0 + r;
            int drow;
            if (cin) drow = (colidx % cdiv) * cmul + colidx / cdiv;
            else     drow = colidx;
            dst[dbase + drow * NO + r0 + c] = ts[c * 33 + r];
        }
    } else {
        bid -= 1224;
        const int wid = tid >> 5, lane = tid & 31;
        int code0 = bid * 32 + wid * 4;
        #pragma unroll
        for (int cc = 0; cc < 4; cc++) {
            const float* p = cb + (code0 + cc) * CBD;
            float v1 = p[lane], v2 = p[lane + 32];
            float s = fmaf(v1, v1, v2 * v2);
            #pragma unroll
            for (int off = 16; off > 0; off >>= 1)
                s += __shfl_down_sync(0xFFFFFFFFu, s, off);
            if (lane == 0) g_cn[code0 + cc] = 0.5f * s;
        }
    }
}

// ---------------------------------------------------------------------------
// conv1: audio -> g_a1 [pos][11][64], elu applied. 8 positions per block.
// ---------------------------------------------------------------------------
__global__ __launch_bounds__(256) void conv1_kernel(
    const float* __restrict__ audio,
    const float* __restrict__ w1c, const float* __restrict__ b1c,
    float* __restrict__ out)
{
    __shared__ float aud[8 * 17];
    __shared__ float w1s[64 * 7];
    const int tid = threadIdx.x;
    const int pos0 = blockIdx.x * 8;

    for (int idx = tid; idx < 64 * 7; idx += 256) w1s[idx] = w1c[idx];
    for (int idx = tid; idx < 8 * 17; idx += 256) {
        int p = idx / 17, u = idx - p * 17;
        int pos = pos0 + p;
        int b = pos / TS, t = pos - b * TS;
        aud[idx] = audio[b * T + t * 240 + 223 + u];
    }
    __syncthreads();

    for (int idx = tid; idx < 8 * 11 * 64; idx += 256) {
        int ch = idx & 63;
        int r = idx >> 6;
        int j = r % 11, p = r / 11;
        float acc = b1c[ch];
        #pragma unroll
        for (int k = 0; k < 7; k++) acc = fmaf(w1s[ch * 7 + k], aud[p * 17 + j + k], acc);
        g_a1[(pos0 + p) * 704 + j * 64 + ch] = elu1(acc);
    }

    if (blockIdx.x == 0 && tid < 24) {
        int b = tid / 6, u = tid % 6;
        out[OFF_S1 + tid] = audio[b * T + (T - 6) + u];
    }
}

// ---------------------------------------------------------------------------
// GEMM-style conv: plain FFMA (FFMA2 measured slower), BM=16, BN=128, KC=32.
// dst[m][n] = elu( sum_k src[rowbase(m)+k] * wt[k][n] + bias[n] )
// rowbase(m) = (m/JDIV)*JMUL + (m%JDIV)*CH. 256 threads. Grids exact (no guards).
// ---------------------------------------------------------------------------
template<int KDIM, int NOUT, int JDIV, int JMUL, int CH>
__global__ __launch_bounds__(256) void gemm_conv(
    const float* __restrict__ src, const float* __restrict__ wt,
    const float* __restrict__ bias, float* __restrict__ dst)
{
    __shared__ float actS[32 * 20];   // [k][row], pitch 20 (16B-aligned rows)
    const int tid = threadIdx.x;
    const int o = tid & 127;
    const int mh = tid >> 7;          // rows mh*8 .. mh*8+7
    const int n0 = blockIdx.y * 128;
    const int m0 = blockIdx.x * 16;

    float acc[8];
    #pragma unroll
    for (int i = 0; i < 8; i++) acc[i] = 0.f;

    // act loader: row lr (0..15), float2 slot kq (0..15) => k = 2*kq
    const int lr = tid >> 4;
    const int kq = tid & 15;
    const int m = m0 + lr;
    const float* sp = src + (m / JDIV) * JMUL + (m % JDIV) * CH;

    for (int kc0 = 0; kc0 < KDIM; kc0 += 32) {
        float2 v = *(const float2*)(sp + kc0 + kq * 2);
        actS[(kq * 2 + 0) * 20 + lr] = v.x;
        actS[(kq * 2 + 1) * 20 + lr] = v.y;
        __syncthreads();

        #pragma unroll
        for (int h2 = 0; h2 < 2; h2++) {
            float wr[16];
            #pragma unroll
            for (int kk = 0; kk < 16; kk++)
                wr[kk] = wt[(kc0 + h2 * 16 + kk) * NOUT + n0 + o];
            #pragma unroll
            for (int kk = 0; kk < 16; kk++) {
                const float* ap = actS + (h2 * 16 + kk) * 20 + mh * 8;
                float4 a0 = *(const float4*)(ap + 0);
                float4 a1 = *(const float4*)(ap + 4);
                float w = wr[kk];
                acc[0] = fmaf(w, a0.x, acc[0]); acc[1] = fmaf(w, a0.y, acc[1]);
                acc[2] = fmaf(w, a0.z, acc[2]); acc[3] = fmaf(w, a0.w, acc[3]);
                acc[4] = fmaf(w, a1.x, acc[4]); acc[5] = fmaf(w, a1.y, acc[5]);
                acc[6] = fmaf(w, a1.z, acc[6]); acc[7] = fmaf(w, a1.w, acc[7]);
            }
        }
        __syncthreads();
    }

    float bb = bias[n0 + o];
    #pragma unroll
    for (int i = 0; i < 8; i++)
        dst[(m0 + mh * 8 + i) * NOUT + n0 + o] = elu1(acc[i] + bb);
}

// ---------------------------------------------------------------------------
// tail: s2/s3/s4 (last position per batch). budget 256+512+512 = 1280/batch
// ---------------------------------------------------------------------------
__global__ void tail_kernel(float* __restrict__ out) {
    int idx = blockIdx.x * blockDim.x + threadIdx.x;
    if (idx >= 4 * 1280) return;
    int b = idx / 1280;
    int r = idx - b * 1280;
    int pos = b * TS + (TS - 1);
    if (r < 256) {
        int c = r >> 2, u = r & 3;
        out[OFF_S2 + (b * 64 + c) * 4 + u] = g_a1[pos * 704 + (7 + u) * 64 + c];
    } else if (r < 768) {
        int rr = r - 256;
        int c = rr >> 2, u = rr & 3;
        out[OFF_S3 + (b * 128 + c) * 4 + u] = g_a2[pos * 896 + (3 + u) * 128 + c];
    } else {
        int rr = r - 768;
        int c = rr >> 1, u = rr & 1;
        out[OFF_S4 + (b * 256 + c) * 2 + u] = g_a3[pos * 768 + (1 + u) * 256 + c];
    }
}

// ---------------------------------------------------------------------------
// rvq + head: 512 threads/block (16 warps) for latency hiding.
// Each thread handles 2 codes (tid, tid+512). Head split-D across thread halves.
// ---------------------------------------------------------------------------
#define RP 10
#define PH 5
__global__ __launch_bounds__(512) void rvq_kernel(
    const float* __restrict__ cb,
    const float* __restrict__ hb,
    float* __restrict__ out)
{
    __shared__ float zblk[RP * DM];                 // [p][d]; reused as head scratch
    __shared__ float2 zq2[DM * PH];                 // [dm][ph]
    __shared__ float2 rs2[CBD * PH];                // [d][ph]
    __shared__ unsigned long long cand[RP * 16];
    __shared__ unsigned long long bestk[RP];

    const int tid = threadIdx.x;
    const int lane = tid & 31;
    const int wid = tid >> 5;                       // 0..15
    const int b = blockIdx.x / 30;
    const int g = blockIdx.x % 30;

    for (int idx = tid; idx < RP * DM; idx += 512) {
        int p = idx >> 9;
        zblk[idx] = g_z[(b * TS + g * RP + p) * DM + (idx & 511)];
    }
    __syncthreads();
    for (int idx = tid; idx < CBD * PH; idx += 512) {
        int d = idx / PH, ph = idx - d * PH;
        rs2[idx] = make_float2(zblk[(2 * ph) * DM + d], zblk[(2 * ph + 1) * DM + d]);
    }
    __syncthreads();

    const unsigned long long* rsu = (const unsigned long long*)rs2;

    for (int i = 0; i < NCB; i++) {
        const float* cbti = g_cbt + i * CBD * CBS;
        unsigned long long dot2[2][PH];
        #pragma unroll
        for (int q = 0; q < 2; q++)
            #pragma unroll
            for (int ph = 0; ph < PH; ph++) dot2[q][ph] = 0ull;

        for (int d = 0; d < CBD; d++) {
            unsigned long long cp[2];
            #pragma unroll
            for (int q = 0; q < 2; q++) {
                float cv = cbti[d * CBS + tid + q * 512];
                cp[q] = pack2(cv, cv);
            }
            unsigned long long rv[PH];
            #pragma unroll
            for (int ph = 0; ph < PH; ph++) rv[ph] = rsu[d * PH + ph];
            #pragma unroll
            for (int q = 0; q < 2; q++)
                #pragma unroll
                for (int ph = 0; ph < PH; ph++)
                    fma2(dot2[q][ph], cp[q], rv[ph]);
        }

        // argmax(dot - 0.5|c|^2) == argmin(dist); key packs (score, ~code)
        unsigned long long best[RP];
        #pragma unroll
        for (int p = 0; p < RP; p++) best[p] = 0ull;
        #pragma unroll
        for (int q = 0; q < 2; q++) {
            int code = tid + q * 512;
            float cn = g_cn[i * CBS + code];
            unsigned invc = ~(unsigned)code;
            #pragma unroll
            for (int ph = 0; ph < PH; ph++) {
                float sc0 = lo32(dot2[q][ph]) - cn;
                float sc1 = hi32(dot2[q][ph]) - cn;
                unsigned long long k0 = (((unsigned long long)fordu(sc0)) << 32) | invc;
                unsigned long long k1 = (((unsigned long long)fordu(sc1)) << 32) | invc;
                if (k0 > best[2 * ph])     best[2 * ph] = k0;
                if (k1 > best[2 * ph + 1]) best[2 * ph + 1] = k1;
            }
        }
        #pragma unroll
        for (int off = 16; off > 0; off >>= 1) {
            #pragma unroll
            for (int p = 0; p < RP; p++) {
                unsigned long long other = __shfl_down_sync(0xFFFFFFFFu, best[p], off);
                if (other > best[p]) best[p] = other;
            }
        }
        if (lane == 0) {
            #pragma unroll
            for (int p = 0; p < RP; p++) cand[p * 16 + wid] = best[p];
        }
        __syncthreads();
        if (tid < RP) {
            unsigned long long m = cand[tid * 16];
            #pragma unroll
            for (int w = 1; w < 16; w++) {
                unsigned long long v = cand[tid * 16 + w];
                if (v > m) m = v;
            }
            bestk[tid] = m;
            unsigned code = ~(unsigned)(m & 0xFFFFFFFFull);
            out[OFF_A + (b * NCB + i) * TS + g * RP + tid] = (float)code;
        }
        __syncthreads();
        // q into zq2 (paired), residual r = z[i+1] + (r - q)
        for (int idx = tid; idx < CBD * PH; idx += 512) {
            int d = idx / PH, ph = idx - d * PH;
            int p0 = 2 * ph, p1 = p0 + 1;
            unsigned c0 = ~(unsigned)(bestk[p0] & 0xFFFFFFFFull);
            unsigned c1 = ~(unsigned)(bestk[p1] & 0xFFFFFFFFull);
            float q0 = cb[(i * CBS + c0) * CBD + d];
            float q1 = cb[(i * CBS + c1) * CBD + d];
            zq2[(i * 64 + d) * PH + ph] = make_float2(q0, q1);
            if (i < NCB - 1) {
                float2 r = rs2[idx];
                rs2[idx] = make_float2(
                    zblk[p0 * DM + (i + 1) * 64 + d] + r.x - q0,
                    zblk[p1 * DM + (i + 1) * 64 + d] + r.y - q1);
            }
        }
        __syncthreads();
    }

    // head split-D: half 0 does d[0,256), half 1 does d[256,512).
    // half 1 parks its partials in zblk (no longer needed), half 0 combines.
    {
        const int half = tid >> 8;          // 0/1
        const int ho = tid & 255;           // output index (h*64+o)
        unsigned long long acc2[PH];
        #pragma unroll
        for (int ph = 0; ph < PH; ph++) acc2[ph] = 0ull;
        const unsigned long long* zqu = (const unsigned long long*)zq2;
        const int d0 = half * 256;
        for (int dm = d0; dm < d0 + 256; dm++) {
            float w = g_hwt[dm * 256 + ho];
            unsigned long long wp = pack2(w, w);
            #pragma unroll
            for (int ph = 0; ph < PH; ph++)
                fma2(acc2[ph], wp, zqu[dm * PH + ph]);
        }
        unsigned long long* ps = (unsigned long long*)zblk;   // scratch 256*PH u64 = 10KB
        if (half == 1) {
            #pragma unroll
            for (int ph = 0; ph < PH; ph++) ps[ho * PH + ph] = acc2[ph];
        }
        __syncthreads();
        if (half == 0) {
            int h = ho >> 6, o = ho & 63;
            float bb = hb[ho];
            #pragma unroll
            for (int ph = 0; ph < PH; ph++) {
                unsigned long long other = ps[ho * PH + ph];
                int p0 = 2 * ph, p1 = p0 + 1;
                float v0 = lo32(acc2[ph]) + lo32(other) + bb;
                float v1 = hi32(acc2[ph]) + hi32(other) + bb;
                out[OFF_BL + ((b * 4 + h) * TS + g * RP + p0) * 64 + o] = v0;
                out[OFF_BL + ((b * 4 + h) * TS + g * RP + p1) * 64 + o] = v1;
            }
        }
    }
}

// ---------------------------------------------------------------------------
extern "C" void kernel_launch(void* const* d_in, const int* in_sizes, int n_in,
                              void* d_out, int out_size)
{
    const float* audio = (const float*)d_in[0];
    const float* w1 = (const float*)d_in[1];
    const float* b1 = (const float*)d_in[2];
    const float* w2 = (const float*)d_in[3];
    const float* b2 = (const float*)d_in[4];
    const float* w3 = (const float*)d_in[5];
    const float* b3 = (const float*)d_in[6];
    const float* w4 = (const float*)d_in[7];
    const float* b4 = (const float*)d_in[8];
    const float* cb = (const float*)d_in[9];
    const float* hw = (const float*)d_in[10];
    const float* hb = (const float*)d_in[11];
    float* out = (float*)d_out;

    prep_kernel<<<1480, 256>>>(w2, w3, w4, hw, cb);
    conv1_kernel<<<150, 256>>>(audio, w1, b1, out);

    float* g_a1p; cudaGetSymbolAddress((void**)&g_a1p, g_a1);
    float* g_a2p; cudaGetSymbolAddress((void**)&g_a2p, g_a2);
    float* g_a3p; cudaGetSymbolAddress((void**)&g_a3p, g_a3);
    float* g_zp;  cudaGetSymbolAddress((void**)&g_zp, g_z);
    float* g_w2tp; cudaGetSymbolAddress((void**)&g_w2tp, g_w2t);
    float* g_w3tp; cudaGetSymbolAddress((void**)&g_w3tp, g_w3t);
    float* g_w4tp; cudaGetSymbolAddress((void**)&g_w4tp, g_w4t);

    // BM=16: grids are exact (8400/16=525, 3600/16=225, 1200/16=75)
    gemm_conv<320, 128, 7, 704, 64><<<dim3(525, 1), 256>>>(g_a1p, g_w2tp, b2, g_a2p);
    gemm_conv<640, 256, 3, 896, 128><<<dim3(225, 2), 256>>>(g_a2p, g_w3tp, b3, g_a3p);
    gemm_conv<768, 512, 1, 768, 0><<<dim3(75, 4), 256>>>(g_a3p, g_w4tp, b4, g_zp);

    tail_kernel<<<20, 256>>>(out);
    rvq_kernel<<<120, 512>>>(cb, hb, out);
}

// round 8
// speedup vs baseline: 1.3587x; 1.2332x over previous
#include <cuda_runtime.h>
#include <math.h>

#define NB 4
#define T 72000
#define TS 300
#define NCB 8
#define CBS 1024
#define CBD 64
#define DM 512

// out offsets (floats): a_tokens, b_logits, s1, s2, s3, s4
#define OFF_A  0
#define OFF_BL 9600
#define OFF_S1 316800
#define OFF_S2 316824
#define OFF_S3 317848
#define OFF_S4 319896

#define NPOS (NB * TS)   // 1200

__device__ float g_z[NPOS * DM];          // encoder output z
__device__ float g_cn[NCB * CBS];         // 0.5*|c|^2
__device__ float g_w2t[320 * 128];        // [(kk*64+i)][o]
__device__ float g_w3t[640 * 256];        // [(kk*128+i)][o]
__device__ float g_w4t[768 * 512];        // [(kk*256+i)][o]
__device__ float g_hwt[DM * 256];         // [d][h*64+o]
__device__ float g_cbt[NCB * CBD * CBS];  // [i][d][code]
__device__ float g_a1[NPOS * 11 * 64];    // elu(conv1) [pos][off 0..10][ch]
__device__ float g_a2[NPOS * 7 * 128];    // elu(conv2) [pos][off 0..6][ch]
__device__ float g_a3[NPOS * 3 * 256];    // elu(conv3) [pos][off 0..2][ch]

__device__ __forceinline__ float elu1(float x) { return x > 0.f ? x : expm1f(x); }

__device__ __forceinline__ unsigned fordu(float f) {
    unsigned u = __float_as_uint(f);
    return u ^ (unsigned)(((int)u >> 31) | 0x80000000);
}

// packed f32x2 helpers (rvq dot phase)
__device__ __forceinline__ unsigned long long pack2(float lo, float hi) {
    unsigned long long r;
    asm("mov.b64 %0, {%1, %2};" : "=l"(r) : "f"(lo), "f"(hi));
    return r;
}
__device__ __forceinline__ void fma2(unsigned long long& d,
                                     unsigned long long a, unsigned long long b) {
    asm("fma.rn.f32x2 %0, %1, %2, %0;" : "+l"(d) : "l"(a), "l"(b));
}
__device__ __forceinline__ float lo32(unsigned long long v) {
    return __uint_as_float((unsigned)v);
}
__device__ __forceinline__ float hi32(unsigned long long v) {
    return __uint_as_float((unsigned)(v >> 32));
}

// ---------------------------------------------------------------------------
// prep: tiled transposes (coalesced both ways) + code half-norms
// ---------------------------------------------------------------------------
__global__ __launch_bounds__(256) void prep_kernel(
    const float* __restrict__ w2, const float* __restrict__ w3,
    const float* __restrict__ w4, const float* __restrict__ hw,
    const float* __restrict__ cb)
{
    __shared__ float ts[32 * 33];
    const int tid = threadIdx.x;
    int bid = blockIdx.x;

    if (bid < 1224) {
        const float* src; float* dst;
        int r0, c0, SP, NO, cdiv, cmul, cin, dbase = 0;
        if (bid < 40) {                // w2: src 128x320 -> dst[(kk*64+i)][o]
            src = w2; dst = g_w2t; SP = 320; NO = 128; cdiv = 5; cmul = 64; cin = 1;
            r0 = (bid & 3) * 32; c0 = (bid >> 2) * 32;
        } else if (bid < 200) {        // w3: 256x640
            bid -= 40;
            src = w3; dst = g_w3t; SP = 640; NO = 256; cdiv = 5; cmul = 128; cin = 1;
            r0 = (bid & 7) * 32; c0 = (bid >> 3) * 32;
        } else if (bid < 584) {        // w4: 512x768
            bid -= 200;
            src = w4; dst = g_w4t; SP = 768; NO = 512; cdiv = 3; cmul = 256; cin = 1;
            r0 = (bid & 15) * 32; c0 = (bid >> 4) * 32;
        } else if (bid < 712) {        // hw: 256x512 plain transpose
            bid -= 584;
            src = hw; dst = g_hwt; SP = 512; NO = 256; cdiv = 1; cmul = 1; cin = 0;
            r0 = (bid & 7) * 32; c0 = (bid >> 3) * 32;
        } else {                       // cb: per-codebook 1024x64 plain transpose
            bid -= 712;
            int i = bid >> 6; int t = bid & 63;
            src = cb + i * 65536; dst = g_cbt; dbase = i * 65536;
            SP = 64; NO = 1024; cdiv = 1; cmul = 1; cin = 0;
            r0 = (t >> 1) * 32; c0 = (t & 1) * 32;
        }
        for (int l = tid; l < 1024; l += 256) {
            int r = l >> 5, c = l & 31;
            ts[r * 33 + c] = src[(r0 + r) * SP + c0 + c];
        }
        __syncthreads();
        for (int l = tid; l < 1024; l += 256) {
            int r = l >> 5, c = l & 31;
            int colidx = c0 + r;
            int drow;
            if (cin) drow = (colidx % cdiv) * cmul + colidx / cdiv;
            else     drow = colidx;
            dst[dbase + drow * NO + r0 + c] = ts[c * 33 + r];
        }
    } else {
        bid -= 1224;
        const int wid = tid >> 5, lane = tid & 31;
        int code0 = bid * 32 + wid * 4;
        #pragma unroll
        for (int cc = 0; cc < 4; cc++) {
            const float* p = cb + (code0 + cc) * CBD;
            float v1 = p[lane], v2 = p[lane + 32];
            float s = fmaf(v1, v1, v2 * v2);
            #pragma unroll
            for (int off = 16; off > 0; off >>= 1)
                s += __shfl_down_sync(0xFFFFFFFFu, s, off);
            if (lane == 0) g_cn[code0 + cc] = 0.5f * s;
        }
    }
}

// ---------------------------------------------------------------------------
// conv1: audio -> g_a1 [pos][11][64], elu applied. 8 positions per block.
// ---------------------------------------------------------------------------
__global__ __launch_bounds__(256) void conv1_kernel(
    const float* __restrict__ audio,
    const float* __restrict__ w1c, const float* __restrict__ b1c,
    float* __restrict__ out)
{
    __shared__ float aud[8 * 17];
    __shared__ float w1s[64 * 7];
    const int tid = threadIdx.x;
    const int pos0 = blockIdx.x * 8;

    for (int idx = tid; idx < 64 * 7; idx += 256) w1s[idx] = w1c[idx];
    for (int idx = tid; idx < 8 * 17; idx += 256) {
        int p = idx / 17, u = idx - p * 17;
        int pos = pos0 + p;
        int b = pos / TS, t = pos - b * TS;
        aud[idx] = audio[b * T + t * 240 + 223 + u];
    }
    __syncthreads();

    for (int idx = tid; idx < 8 * 11 * 64; idx += 256) {
        int ch = idx & 63;
        int r = idx >> 6;
        int j = r % 11, p = r / 11;
        float acc = b1c[ch];
        #pragma unroll
        for (int k = 0; k < 7; k++) acc = fmaf(w1s[ch * 7 + k], aud[p * 17 + j + k], acc);
        g_a1[(pos0 + p) * 704 + j * 64 + ch] = elu1(acc);
    }

    if (blockIdx.x == 0 && tid < 24) {
        int b = tid / 6, u = tid % 6;
        out[OFF_S1 + tid] = audio[b * T + (T - 6) + u];
    }
}

// ---------------------------------------------------------------------------
// smem-smem GEMM conv: BM=64, BN=64, BK=16, 256 thr, 4x4 reg tile, dbl-buffered.
// dst[m][n] = elu( sum_k src[rowbase(m)+k] * wt[k][n] + bias[n] )
// rowbase(m) = (m/JDIV)*JMUL + (m%JDIV)*CH
// ---------------------------------------------------------------------------
#define GP 68   // smem pitch (floats) for 64-wide tiles; 68*4B = 16B-aligned rows
template<int KDIM, int NOUT, int MROWS, int JDIV, int JMUL, int CH>
__global__ __launch_bounds__(256) void gemm_conv(
    const float* __restrict__ src, const float* __restrict__ wt,
    const float* __restrict__ bias, float* __restrict__ dst)
{
    __shared__ float As[2][16 * GP];   // [k][m]
    __shared__ float Bs[2][16 * GP];   // [k][n]

    const int tid = threadIdx.x;
    const int tx = tid & 15;           // n-tile index
    const int ty = tid >> 4;           // m-tile index
    const int m0 = blockIdx.x * 64;
    const int n0 = blockIdx.y * 64;

    // A loader: m_l = tid%64, k4 = tid/64 (covers k = 4*k4 .. 4*k4+3)
    const int m_l = tid & 63;
    const int k4 = tid >> 6;
    int mrow = m0 + m_l; if (mrow >= MROWS) mrow = MROWS - 1;   // clamp (stores guarded)
    const float* spA = src + (mrow / JDIV) * JMUL + (mrow % JDIV) * CH;

    // B loader: k_l = tid/16 (0..15), n4 = tid%16
    const int k_l = tid >> 4;
    const int n4 = tid & 15;
    const float* spB = wt + k_l * NOUT + n0 + n4 * 4;

    float acc[4][4];
    #pragma unroll
    for (int i = 0; i < 4; i++)
        #pragma unroll
        for (int j = 0; j < 4; j++) acc[i][j] = 0.f;

    // prologue: chunk 0 into buffer 0
    float4 av = *(const float4*)(spA + k4 * 4);
    float4 bv = *(const float4*)(spB);
    {
        float* A0 = As[0]; float* B0 = Bs[0];
        A0[(k4 * 4 + 0) * GP + m_l] = av.x;
        A0[(k4 * 4 + 1) * GP + m_l] = av.y;
        A0[(k4 * 4 + 2) * GP + m_l] = av.z;
        A0[(k4 * 4 + 3) * GP + m_l] = av.w;
        *(float4*)(B0 + k_l * GP + n4 * 4) = bv;
    }
    __syncthreads();

    int buf = 0;
    for (int kc0 = 0; kc0 < KDIM; kc0 += 16) {
        const bool have_next = (kc0 + 16 < KDIM);
        if (have_next) {
            av = *(const float4*)(spA + kc0 + 16 + k4 * 4);
            bv = *(const float4*)(spB + (kc0 + 16) * NOUT);
        }

        const float* A = As[buf];
        const float* B = Bs[buf];
        #pragma unroll
        for (int k = 0; k < 16; k++) {
            float4 a = *(const float4*)(A + k * GP + ty * 4);
            float4 b = *(const float4*)(B + k * GP + tx * 4);
            acc[0][0] = fmaf(a.x, b.x, acc[0][0]); acc[0][1] = fmaf(a.x, b.y, acc[0][1]);
            acc[0][2] = fmaf(a.x, b.z, acc[0][2]); acc[0][3] = fmaf(a.x, b.w, acc[0][3]);
            acc[1][0] = fmaf(a.y, b.x, acc[1][0]); acc[1][1] = fmaf(a.y, b.y, acc[1][1]);
            acc[1][2] = fmaf(a.y, b.z, acc[1][2]); acc[1][3] = fmaf(a.y, b.w, acc[1][3]);
            acc[2][0] = fmaf(a.z, b.x, acc[2][0]); acc[2][1] = fmaf(a.z, b.y, acc[2][1]);
            acc[2][2] = fmaf(a.z, b.z, acc[2][2]); acc[2][3] = fmaf(a.z, b.w, acc[2][3]);
            acc[3][0] = fmaf(a.w, b.x, acc[3][0]); acc[3][1] = fmaf(a.w, b.y, acc[3][1]);
            acc[3][2] = fmaf(a.w, b.z, acc[3][2]); acc[3][3] = fmaf(a.w, b.w, acc[3][3]);
        }

        if (have_next) {
            float* An = As[buf ^ 1]; float* Bn = Bs[buf ^ 1];
            An[(k4 * 4 + 0) * GP + m_l] = av.x;
            An[(k4 * 4 + 1) * GP + m_l] = av.y;
            An[(k4 * 4 + 2) * GP + m_l] = av.z;
            An[(k4 * 4 + 3) * GP + m_l] = av.w;
            *(float4*)(Bn + k_l * GP + n4 * 4) = bv;
        }
        __syncthreads();
        buf ^= 1;
    }

    float4 bb = *(const float4*)(bias + n0 + tx * 4);
    #pragma unroll
    for (int i = 0; i < 4; i++) {
        int m = m0 + ty * 4 + i;
        if (m < MROWS) {
            float4 v;
            v.x = elu1(acc[i][0] + bb.x);
            v.y = elu1(acc[i][1] + bb.y);
            v.z = elu1(acc[i][2] + bb.z);
            v.w = elu1(acc[i][3] + bb.w);
            *(float4*)(dst + m * NOUT + n0 + tx * 4) = v;
        }
    }
}

// ---------------------------------------------------------------------------
// tail: s2/s3/s4 (last position per batch). budget 256+512+512 = 1280/batch
// ---------------------------------------------------------------------------
__global__ void tail_kernel(float* __restrict__ out) {
    int idx = blockIdx.x * blockDim.x + threadIdx.x;
    if (idx >= 4 * 1280) return;
    int b = idx / 1280;
    int r = idx - b * 1280;
    int pos = b * TS + (TS - 1);
    if (r < 256) {
        int c = r >> 2, u = r & 3;
        out[OFF_S2 + (b * 64 + c) * 4 + u] = g_a1[pos * 704 + (7 + u) * 64 + c];
    } else if (r < 768) {
        int rr = r - 256;
        int c = rr >> 2, u = rr & 3;
        out[OFF_S3 + (b * 128 + c) * 4 + u] = g_a2[pos * 896 + (3 + u) * 128 + c];
    } else {
        int rr = r - 768;
        int c = rr >> 1, u = rr & 1;
        out[OFF_S4 + (b * 256 + c) * 2 + u] = g_a3[pos * 768 + (1 + u) * 256 + c];
    }
}

// ---------------------------------------------------------------------------
// rvq + head: 512 threads/block (unchanged from R7, which passed)
// ---------------------------------------------------------------------------
#define RP 10
#define PH 5
__global__ __launch_bounds__(512) void rvq_kernel(
    const float* __restrict__ cb,
    const float* __restrict__ hb,
    float* __restrict__ out)
{
    __shared__ float zblk[RP * DM];                 // [p][d]; reused as head scratch
    __shared__ float2 zq2[DM * PH];                 // [dm][ph]
    __shared__ float2 rs2[CBD * PH];                // [d][ph]
    __shared__ unsigned long long cand[RP * 16];
    __shared__ unsigned long long bestk[RP];

    const int tid = threadIdx.x;
    const int lane = tid & 31;
    const int wid = tid >> 5;
    const int b = blockIdx.x / 30;
    const int g = blockIdx.x % 30;

    for (int idx = tid; idx < RP * DM; idx += 512) {
        int p = idx >> 9;
        zblk[idx] = g_z[(b * TS + g * RP + p) * DM + (idx & 511)];
    }
    __syncthreads();
    for (int idx = tid; idx < CBD * PH; idx += 512) {
        int d = idx / PH, ph = idx - d * PH;
        rs2[idx] = make_float2(zblk[(2 * ph) * DM + d], zblk[(2 * ph + 1) * DM + d]);
    }
    __syncthreads();

    const unsigned long long* rsu = (const unsigned long long*)rs2;

    for (int i = 0; i < NCB; i++) {
        const float* cbti = g_cbt + i * CBD * CBS;
        unsigned long long dot2[2][PH];
        #pragma unroll
        for (int q = 0; q < 2; q++)
            #pragma unroll
            for (int ph = 0; ph < PH; ph++) dot2[q][ph] = 0ull;

        for (int d = 0; d < CBD; d++) {
            unsigned long long cp[2];
            #pragma unroll
            for (int q = 0; q < 2; q++) {
                float cv = cbti[d * CBS + tid + q * 512];
                cp[q] = pack2(cv, cv);
            }
            unsigned long long rv[PH];
            #pragma unroll
            for (int ph = 0; ph < PH; ph++) rv[ph] = rsu[d * PH + ph];
            #pragma unroll
            for (int q = 0; q < 2; q++)
                #pragma unroll
                for (int ph = 0; ph < PH; ph++)
                    fma2(dot2[q][ph], cp[q], rv[ph]);
        }

        unsigned long long best[RP];
        #pragma unroll
        for (int p = 0; p < RP; p++) best[p] = 0ull;
        #pragma unroll
        for (int q = 0; q < 2; q++) {
            int code = tid + q * 512;
            float cn = g_cn[i * CBS + code];
            unsigned invc = ~(unsigned)code;
            #pragma unroll
            for (int ph = 0; ph < PH; ph++) {
                float sc0 = lo32(dot2[q][ph]) - cn;
                float sc1 = hi32(dot2[q][ph]) - cn;
                unsigned long long k0 = (((unsigned long long)fordu(sc0)) << 32) | invc;
                unsigned long long k1 = (((unsigned long long)fordu(sc1)) << 32) | invc;
                if (k0 > best[2 * ph])     best[2 * ph] = k0;
                if (k1 > best[2 * ph + 1]) best[2 * ph + 1] = k1;
            }
        }
        #pragma unroll
        for (int off = 16; off > 0; off >>= 1) {
            #pragma unroll
            for (int p = 0; p < RP; p++) {
                unsigned long long other = __shfl_down_sync(0xFFFFFFFFu, best[p], off);
                if (other > best[p]) best[p] = other;
            }
        }
        if (lane == 0) {
            #pragma unroll
            for (int p = 0; p < RP; p++) cand[p * 16 + wid] = best[p];
        }
        __syncthreads();
        if (tid < RP) {
            unsigned long long m = cand[tid * 16];
            #pragma unroll
            for (int w = 1; w < 16; w++) {
                unsigned long long v = cand[tid * 16 + w];
                if (v > m) m = v;
            }
            bestk[tid] = m;
            unsigned code = ~(unsigned)(m & 0xFFFFFFFFull);
            out[OFF_A + (b * NCB + i) * TS + g * RP + tid] = (float)code;
        }
        __syncthreads();
        for (int idx = tid; idx < CBD * PH; idx += 512) {
            int d = idx / PH, ph = idx - d * PH;
            int p0 = 2 * ph, p1 = p0 + 1;
            unsigned c0 = ~(unsigned)(bestk[p0] & 0xFFFFFFFFull);
            unsigned c1 = ~(unsigned)(bestk[p1] & 0xFFFFFFFFull);
            float q0 = cb[(i * CBS + c0) * CBD + d];
            float q1 = cb[(i * CBS + c1) * CBD + d];
            zq2[(i * 64 + d) * PH + ph] = make_float2(q0, q1);
            if (i < NCB - 1) {
                float2 r = rs2[idx];
                rs2[idx] = make_float2(
                    zblk[p0 * DM + (i + 1) * 64 + d] + r.x - q0,
                    zblk[p1 * DM + (i + 1) * 64 + d] + r.y - q1);
            }
        }
        __syncthreads();
    }

    // head split-D across the two 256-thread halves; combine via smem scratch
    {
        const int half = tid >> 8;
        const int ho = tid & 255;
        unsigned long long acc2[PH];
        #pragma unroll
        for (int ph = 0; ph < PH; ph++) acc2[ph] = 0ull;
        const unsigned long long* zqu = (const unsigned long long*)zq2;
        const int d0 = half * 256;
        for (int dm = d0; dm < d0 + 256; dm++) {
            float w = g_hwt[dm * 256 + ho];
            unsigned long long wp = pack2(w, w);
            #pragma unroll
            for (int ph = 0; ph < PH; ph++)
                fma2(acc2[ph], wp, zqu[dm * PH + ph]);
        }
        unsigned long long* ps = (unsigned long long*)zblk;
        if (half == 1) {
            #pragma unroll
            for (int ph = 0; ph < PH; ph++) ps[ho * PH + ph] = acc2[ph];
        }
        __syncthreads();
        if (half == 0) {
            int h = ho >> 6, o = ho & 63;
            float bb = hb[ho];
            #pragma unroll
            for (int ph = 0; ph < PH; ph++) {
                unsigned long long other = ps[ho * PH + ph];
                int p0 = 2 * ph, p1 = p0 + 1;
                float v0 = lo32(acc2[ph]) + lo32(other) + bb;
                float v1 = hi32(acc2[ph]) + hi32(other) + bb;
                out[OFF_BL + ((b * 4 + h) * TS + g * RP + p0) * 64 + o] = v0;
                out[OFF_BL + ((b * 4 + h) * TS + g * RP + p1) * 64 + o] = v1;
            }
        }
    }
}

// ---------------------------------------------------------------------------
extern "C" void kernel_launch(void* const* d_in, const int* in_sizes, int n_in,
                              void* d_out, int out_size)
{
    const float* audio = (const float*)d_in[0];
    const float* w1 = (const float*)d_in[1];
    const float* b1 = (const float*)d_in[2];
    const float* w2 = (const float*)d_in[3];
    const float* b2 = (const float*)d_in[4];
    const float* w3 = (const float*)d_in[5];
    const float* b3 = (const float*)d_in[6];
    const float* w4 = (const float*)d_in[7];
    const float* b4 = (const float*)d_in[8];
    const float* cb = (const float*)d_in[9];
    const float* hw = (const float*)d_in[10];
    const float* hb = (const float*)d_in[11];
    float* out = (float*)d_out;

    prep_kernel<<<1480, 256>>>(w2, w3, w4, hw, cb);
    conv1_kernel<<<150, 256>>>(audio, w1, b1, out);

    float* g_a1p; cudaGetSymbolAddress((void**)&g_a1p, g_a1);
    float* g_a2p; cudaGetSymbolAddress((void**)&g_a2p, g_a2);
    float* g_a3p; cudaGetSymbolAddress((void**)&g_a3p, g_a3);
    float* g_zp;  cudaGetSymbolAddress((void**)&g_zp, g_z);
    float* g_w2tp; cudaGetSymbolAddress((void**)&g_w2tp, g_w2t);
    float* g_w3tp; cudaGetSymbolAddress((void**)&g_w3tp, g_w3t);
    float* g_w4tp; cudaGetSymbolAddress((void**)&g_w4tp, g_w4t);

    // BM=64, BN=64: grids ceil(M/64) x N/64
    gemm_conv<320, 128, 8400, 7, 704, 64><<<dim3(132, 2), 256>>>(g_a1p, g_w2tp, b2, g_a2p);
    gemm_conv<640, 256, 3600, 3, 896, 128><<<dim3(57, 4), 256>>>(g_a2p, g_w3tp, b3, g_a3p);
    gemm_conv<768, 512, 1200, 1, 768, 0><<<dim3(19, 8), 256>>>(g_a3p, g_w4tp, b4, g_zp);

    tail_kernel<<<20, 256>>>(out);
    rvq_kernel<<<120, 512>>>(cb, hb, out);
}

// round 9
// speedup vs baseline: 1.3855x; 1.0198x over previous
#include <cuda_runtime.h>
#include <math.h>

#define NB 4
#define T 72000
#define TS 300
#define NCB 8
#define CBS 1024
#define CBD 64
#define DM 512

// out offsets (floats): a_tokens, b_logits, s1, s2, s3, s4
#define OFF_A  0
#define OFF_BL 9600
#define OFF_S1 316800
#define OFF_S2 316824
#define OFF_S3 317848
#define OFF_S4 319896

#define NPOS (NB * TS)   // 1200

__device__ float g_cn[NCB * CBS];         // 0.5*|c|^2
__device__ float g_w2t[320 * 128];        // [(kk*64+i)][o]
__device__ float g_w3t[640 * 256];        // [(kk*128+i)][o]
__device__ float g_w4t[768 * 512];        // [(kk*256+i)][o]
__device__ float g_hwt[DM * 256];         // [d][h*64+o]
__device__ float g_cbt[NCB * CBD * CBS];  // [i][d][code]
__device__ float g_a1[NPOS * 11 * 64];    // elu(conv1) [pos][off 0..10][ch]
__device__ float g_a2[NPOS * 7 * 128];    // elu(conv2) [pos][off 0..6][ch]
__device__ float g_a3[NPOS * 3 * 256];    // elu(conv3) [pos][off 0..2][ch]
__device__ float g_zpart[2][NPOS * DM];   // conv4 K-split partials (no bias/elu)

__device__ __forceinline__ float elu1(float x) { return x > 0.f ? x : expm1f(x); }

__device__ __forceinline__ unsigned fordu(float f) {
    unsigned u = __float_as_uint(f);
    return u ^ (unsigned)(((int)u >> 31) | 0x80000000);
}

// packed f32x2 helpers (rvq dot phase)
__device__ __forceinline__ unsigned long long pack2(float lo, float hi) {
    unsigned long long r;
    asm("mov.b64 %0, {%1, %2};" : "=l"(r) : "f"(lo), "f"(hi));
    return r;
}
__device__ __forceinline__ void fma2(unsigned long long& d,
                                     unsigned long long a, unsigned long long b) {
    asm("fma.rn.f32x2 %0, %1, %2, %0;" : "+l"(d) : "l"(a), "l"(b));
}
__device__ __forceinline__ float lo32(unsigned long long v) {
    return __uint_as_float((unsigned)v);
}
__device__ __forceinline__ float hi32(unsigned long long v) {
    return __uint_as_float((unsigned)(v >> 32));
}

// ---------------------------------------------------------------------------
// prep + conv1 merged. blocks [0,1224): transposes, [1224,1480): code norms,
// [1480,1630): conv1 (150 blocks x 8 positions).
// ---------------------------------------------------------------------------
__global__ __launch_bounds__(256) void prep_conv1_kernel(
    const float* __restrict__ w2, const float* __restrict__ w3,
    const float* __restrict__ w4, const float* __restrict__ hw,
    const float* __restrict__ cb,
    const float* __restrict__ audio,
    const float* __restrict__ w1c, const float* __restrict__ b1c,
    float* __restrict__ out)
{
    __shared__ float ts[32 * 33];
    __shared__ float aud[8 * 17];
    __shared__ float w1s[64 * 7];
    const int tid = threadIdx.x;
    int bid = blockIdx.x;

    if (bid < 1224) {
        const float* src; float* dst;
        int r0, c0, SP, NO, cdiv, cmul, cin, dbase = 0;
        if (bid < 40) {                // w2: src 128x320 -> dst[(kk*64+i)][o]
            src = w2; dst = g_w2t; SP = 320; NO = 128; cdiv = 5; cmul = 64; cin = 1;
            r0 = (bid & 3) * 32; c0 = (bid >> 2) * 32;
        } else if (bid < 200) {        // w3: 256x640
            bid -= 40;
            src = w3; dst = g_w3t; SP = 640; NO = 256; cdiv = 5; cmul = 128; cin = 1;
            r0 = (bid & 7) * 32; c0 = (bid >> 3) * 32;
        } else if (bid < 584) {        // w4: 512x768
            bid -= 200;
            src = w4; dst = g_w4t; SP = 768; NO = 512; cdiv = 3; cmul = 256; cin = 1;
            r0 = (bid & 15) * 32; c0 = (bid >> 4) * 32;
        } else if (bid < 712) {        // hw: 256x512 plain transpose
            bid -= 584;
            src = hw; dst = g_hwt; SP = 512; NO = 256; cdiv = 1; cmul = 1; cin = 0;
            r0 = (bid & 7) * 32; c0 = (bid >> 3) * 32;
        } else {                       // cb: per-codebook 1024x64 plain transpose
            bid -= 712;
            int i = bid >> 6; int t = bid & 63;
            src = cb + i * 65536; dst = g_cbt; dbase = i * 65536;
            SP = 64; NO = 1024; cdiv = 1; cmul = 1; cin = 0;
            r0 = (t >> 1) * 32; c0 = (t & 1) * 32;
        }
        for (int l = tid; l < 1024; l += 256) {
            int r = l >> 5, c = l & 31;
            ts[r * 33 + c] = src[(r0 + r) * SP + c0 + c];
        }
        __syncthreads();
        for (int l = tid; l < 1024; l += 256) {
            int r = l >> 5, c = l & 31;
            int colidx = c0 + r;
            int drow;
            if (cin) drow = (colidx % cdiv) * cmul + colidx / cdiv;
            else     drow = colidx;
            dst[dbase + drow * NO + r0 + c] = ts[c * 33 + r];
        }
    } else if (bid < 1480) {
        bid -= 1224;
        const int wid = tid >> 5, lane = tid & 31;
        int code0 = bid * 32 + wid * 4;
        #pragma unroll
        for (int cc = 0; cc < 4; cc++) {
            const float* p = cb + (code0 + cc) * CBD;
            float v1 = p[lane], v2 = p[lane + 32];
            float s = fmaf(v1, v1, v2 * v2);
            #pragma unroll
            for (int off = 16; off > 0; off >>= 1)
                s += __shfl_down_sync(0xFFFFFFFFu, s, off);
            if (lane == 0) g_cn[code0 + cc] = 0.5f * s;
        }
    } else {
        // conv1: 8 positions per block
        bid -= 1480;
        const int pos0 = bid * 8;
        for (int idx = tid; idx < 64 * 7; idx += 256) w1s[idx] = w1c[idx];
        for (int idx = tid; idx < 8 * 17; idx += 256) {
            int p = idx / 17, u = idx - p * 17;
            int pos = pos0 + p;
            int b = pos / TS, t = pos - b * TS;
            aud[idx] = audio[b * T + t * 240 + 223 + u];
        }
        __syncthreads();
        for (int idx = tid; idx < 8 * 11 * 64; idx += 256) {
            int ch = idx & 63;
            int r = idx >> 6;
            int j = r % 11, p = r / 11;
            float acc = b1c[ch];
            #pragma unroll
            for (int k = 0; k < 7; k++) acc = fmaf(w1s[ch * 7 + k], aud[p * 17 + j + k], acc);
            g_a1[(pos0 + p) * 704 + j * 64 + ch] = elu1(acc);
        }
        if (bid == 0 && tid < 24) {
            int b = tid / 6, u = tid % 6;
            out[OFF_S1 + tid] = audio[b * T + (T - 6) + u];
        }
    }
}

// ---------------------------------------------------------------------------
// smem-smem GEMM conv: BM=64, BN=64, BK=16, 256 thr, 4x4 reg tile,
// double-buffered smem + register-pipelined LDS in the inner loop.
// EPI=1: dst = elu(acc + bias). EPI=0: dst = acc (raw partial).
// NSPL: K-splits mapped onto blockIdx.y (y = spl*(NOUT/64) + ntile).
// ---------------------------------------------------------------------------
#define GP 68   // smem pitch (floats); 68*4B rows keep float4 alignment
template<int KDIM, int NOUT, int MROWS, int JDIV, int JMUL, int CH, int EPI, int NSPL>
__global__ __launch_bounds__(256) void gemm_conv(
    const float* __restrict__ src, const float* __restrict__ wt,
    const float* __restrict__ bias, float* __restrict__ dst)
{
    __shared__ float As[2][16 * GP];   // [k][m]
    __shared__ float Bs[2][16 * GP];   // [k][n]

    const int tid = threadIdx.x;
    const int tx = tid & 15;
    const int ty = tid >> 4;
    const int m0 = blockIdx.x * 64;
    int yb = blockIdx.y;
    if (NSPL > 1) {
        int spl = yb / (NOUT / 64);
        yb -= spl * (NOUT / 64);
        src += spl * KDIM;            // valid only when JDIV==1
        wt  += spl * KDIM * NOUT;
        dst += spl * MROWS * NOUT;
    }
    const int n0 = yb * 64;

    const int m_l = tid & 63;
    const int k4 = tid >> 6;
    int mrow = m0 + m_l; if (mrow >= MROWS) mrow = MROWS - 1;   // clamp (stores guarded)
    const float* spA = src + (mrow / JDIV) * JMUL + (mrow % JDIV) * CH;

    const int k_l = tid >> 4;
    const int n4 = tid & 15;
    const float* spB = wt + k_l * NOUT + n0 + n4 * 4;

    float acc[4][4];
    #pragma unroll
    for (int i = 0; i < 4; i++)
        #pragma unroll
        for (int j = 0; j < 4; j++) acc[i][j] = 0.f;

    float4 av = *(const float4*)(spA + k4 * 4);
    float4 bv = *(const float4*)(spB);
    {
        float* A0 = As[0]; float* B0 = Bs[0];
        A0[(k4 * 4 + 0) * GP + m_l] = av.x;
        A0[(k4 * 4 + 1) * GP + m_l] = av.y;
        A0[(k4 * 4 + 2) * GP + m_l] = av.z;
        A0[(k4 * 4 + 3) * GP + m_l] = av.w;
        *(float4*)(B0 + k_l * GP + n4 * 4) = bv;
    }
    __syncthreads();

    int buf = 0;
    for (int kc0 = 0; kc0 < KDIM; kc0 += 16) {
        const bool have_next = (kc0 + 16 < KDIM);
        if (have_next) {
            av = *(const float4*)(spA + kc0 + 16 + k4 * 4);
            bv = *(const float4*)(spB + (kc0 + 16) * NOUT);
        }

        const float* A = As[buf];
        const float* B = Bs[buf];
        // register-pipelined: prefetch k+1 while doing FMAs for k
        float4 a0 = *(const float4*)(A + 0 * GP + ty * 4);
        float4 b0 = *(const float4*)(B + 0 * GP + tx * 4);
        #pragma unroll
        for (int k = 0; k < 16; k++) {
            float4 an, bn;
            if (k < 15) {
                an = *(const float4*)(A + (k + 1) * GP + ty * 4);
                bn = *(const float4*)(B + (k + 1) * GP + tx * 4);
            }
            acc[0][0] = fmaf(a0.x, b0.x, acc[0][0]); acc[0][1] = fmaf(a0.x, b0.y, acc[0][1]);
            acc[0][2] = fmaf(a0.x, b0.z, acc[0][2]); acc[0][3] = fmaf(a0.x, b0.w, acc[0][3]);
            acc[1][0] = fmaf(a0.y, b0.x, acc[1][0]); acc[1][1] = fmaf(a0.y, b0.y, acc[1][1]);
            acc[1][2] = fmaf(a0.y, b0.z, acc[1][2]); acc[1][3] = fmaf(a0.y, b0.w, acc[1][3]);
            acc[2][0] = fmaf(a0.z, b0.x, acc[2][0]); acc[2][1] = fmaf(a0.z, b0.y, acc[2][1]);
            acc[2][2] = fmaf(a0.z, b0.z, acc[2][2]); acc[2][3] = fmaf(a0.z, b0.w, acc[2][3]);
            acc[3][0] = fmaf(a0.w, b0.x, acc[3][0]); acc[3][1] = fmaf(a0.w, b0.y, acc[3][1]);
            acc[3][2] = fmaf(a0.w, b0.z, acc[3][2]); acc[3][3] = fmaf(a0.w, b0.w, acc[3][3]);
            if (k < 15) { a0 = an; b0 = bn; }
        }

        if (have_next) {
            float* An = As[buf ^ 1]; float* Bn = Bs[buf ^ 1];
            An[(k4 * 4 + 0) * GP + m_l] = av.x;
            An[(k4 * 4 + 1) * GP + m_l] = av.y;
            An[(k4 * 4 + 2) * GP + m_l] = av.z;
            An[(k4 * 4 + 3) * GP + m_l] = av.w;
            *(float4*)(Bn + k_l * GP + n4 * 4) = bv;
        }
        __syncthreads();
        buf ^= 1;
    }

    #pragma unroll
    for (int i = 0; i < 4; i++) {
        int m = m0 + ty * 4 + i;
        if (m < MROWS) {
            float4 v;
            if (EPI) {
                float4 bb = *(const float4*)(bias + n0 + tx * 4);
                v.x = elu1(acc[i][0] + bb.x);
                v.y = elu1(acc[i][1] + bb.y);
                v.z = elu1(acc[i][2] + bb.z);
                v.w = elu1(acc[i][3] + bb.w);
            } else {
                v = make_float4(acc[i][0], acc[i][1], acc[i][2], acc[i][3]);
            }
            *(float4*)(dst + m * NOUT + n0 + tx * 4) = v;
        }
    }
}

// ---------------------------------------------------------------------------
// rvq + head; z assembled on load from conv4 K-split partials (+bias, elu).
// blocks [0,120): rvq; [120,130): tail (s2/s3/s4). 512 threads.
// ---------------------------------------------------------------------------
#define RP 10
#define PH 5
__global__ __launch_bounds__(512) void rvq_kernel(
    const float* __restrict__ cb,
    const float* __restrict__ b4c,
    const float* __restrict__ hb,
    float* __restrict__ out)
{
    __shared__ float zblk[RP * DM];                 // [p][d]; reused as head scratch
    __shared__ float2 zq2[DM * PH];                 // [dm][ph]
    __shared__ float2 rs2[CBD * PH];                // [d][ph]
    __shared__ unsigned long long cand[RP * 16];
    __shared__ unsigned long long bestk[RP];

    const int tid = threadIdx.x;

    if (blockIdx.x >= 120) {
        // tail: 10 blocks x 512 = 5120 = 4 batches x 1280
        int idx = (blockIdx.x - 120) * 512 + tid;
        int b = idx / 1280;
        int r = idx - b * 1280;
        int pos = b * TS + (TS - 1);
        if (r < 256) {
            int c = r >> 2, u = r & 3;
            out[OFF_S2 + (b * 64 + c) * 4 + u] = g_a1[pos * 704 + (7 + u) * 64 + c];
        } else if (r < 768) {
            int rr = r - 256;
            int c = rr >> 2, u = rr & 3;
            out[OFF_S3 + (b * 128 + c) * 4 + u] = g_a2[pos * 896 + (3 + u) * 128 + c];
        } else {
            int rr = r - 768;
            int c = rr >> 1, u = rr & 1;
            out[OFF_S4 + (b * 256 + c) * 2 + u] = g_a3[pos * 768 + (1 + u) * 256 + c];
        }
        return;
    }

    const int lane = tid & 31;
    const int wid = tid >> 5;
    const int b = blockIdx.x / 30;
    const int g = blockIdx.x % 30;

    // assemble z = elu(p1 + p2 + bias) on load
    for (int idx = tid; idx < RP * DM; idx += 512) {
        int p = idx >> 9, d = idx & 511;
        int gi = (b * TS + g * RP + p) * DM + d;
        zblk[idx] = elu1(g_zpart[0][gi] + g_zpart[1][gi] + b4c[d]);
    }
    __syncthreads();
    for (int idx = tid; idx < CBD * PH; idx += 512) {
        int d = idx / PH, ph = idx - d * PH;
        rs2[idx] = make_float2(zblk[(2 * ph) * DM + d], zblk[(2 * ph + 1) * DM + d]);
    }
    __syncthreads();

    const unsigned long long* rsu = (const unsigned long long*)rs2;

    for (int i = 0; i < NCB; i++) {
        const float* cbti = g_cbt + i * CBD * CBS;
        unsigned long long dot2[2][PH];
        #pragma unroll
        for (int q = 0; q < 2; q++)
            #pragma unroll
            for (int ph = 0; ph < PH; ph++) dot2[q][ph] = 0ull;

        for (int d = 0; d < CBD; d++) {
            unsigned long long cp[2];
            #pragma unroll
            for (int q = 0; q < 2; q++) {
                float cv = cbti[d * CBS + tid + q * 512];
                cp[q] = pack2(cv, cv);
            }
            unsigned long long rv[PH];
            #pragma unroll
            for (int ph = 0; ph < PH; ph++) rv[ph] = rsu[d * PH + ph];
            #pragma unroll
            for (int q = 0; q < 2; q++)
                #pragma unroll
                for (int ph = 0; ph < PH; ph++)
                    fma2(dot2[q][ph], cp[q], rv[ph]);
        }

        unsigned long long best[RP];
        #pragma unroll
        for (int p = 0; p < RP; p++) best[p] = 0ull;
        #pragma unroll
        for (int q = 0; q < 2; q++) {
            int code = tid + q * 512;
            float cn = g_cn[i * CBS + code];
            unsigned invc = ~(unsigned)code;
            #pragma unroll
            for (int ph = 0; ph < PH; ph++) {
                float sc0 = lo32(dot2[q][ph]) - cn;
                float sc1 = hi32(dot2[q][ph]) - cn;
                unsigned long long k0 = (((unsigned long long)fordu(sc0)) << 32) | invc;
                unsigned long long k1 = (((unsigned long long)fordu(sc1)) << 32) | invc;
                if (k0 > best[2 * ph])     best[2 * ph] = k0;
                if (k1 > best[2 * ph + 1]) best[2 * ph + 1] = k1;
            }
        }
        #pragma unroll
        for (int off = 16; off > 0; off >>= 1) {
            #pragma unroll
            for (int p = 0; p < RP; p++) {
                unsigned long long other = __shfl_down_sync(0xFFFFFFFFu, best[p], off);
                if (other > best[p]) best[p] = other;
            }
        }
        if (lane == 0) {
            #pragma unroll
            for (int p = 0; p < RP; p++) cand[p * 16 + wid] = best[p];
        }
        __syncthreads();
        if (tid < RP) {
            unsigned long long m = cand[tid * 16];
            #pragma unroll
            for (int w = 1; w < 16; w++) {
                unsigned long long v = cand[tid * 16 + w];
                if (v > m) m = v;
            }
            bestk[tid] = m;
            unsigned code = ~(unsigned)(m & 0xFFFFFFFFull);
            out[OFF_A + (b * NCB + i) * TS + g * RP + tid] = (float)code;
        }
        __syncthreads();
        for (int idx = tid; idx < CBD * PH; idx += 512) {
            int d = idx / PH, ph = idx - d * PH;
            int p0 = 2 * ph, p1 = p0 + 1;
            unsigned c0 = ~(unsigned)(bestk[p0] & 0xFFFFFFFFull);
            unsigned c1 = ~(unsigned)(bestk[p1] & 0xFFFFFFFFull);
            float q0 = cb[(i * CBS + c0) * CBD + d];
            float q1 = cb[(i * CBS + c1) * CBD + d];
            zq2[(i * 64 + d) * PH + ph] = make_float2(q0, q1);
            if (i < NCB - 1) {
                float2 r = rs2[idx];
                rs2[idx] = make_float2(
                    zblk[p0 * DM + (i + 1) * 64 + d] + r.x - q0,
                    zblk[p1 * DM + (i + 1) * 64 + d] + r.y - q1);
            }
        }
        __syncthreads();
    }

    // head split-D across the two 256-thread halves; combine via smem scratch
    {
        const int half = tid >> 8;
        const int ho = tid & 255;
        unsigned long long acc2[PH];
        #pragma unroll
        for (int ph = 0; ph < PH; ph++) acc2[ph] = 0ull;
        const unsigned long long* zqu = (const unsigned long long*)zq2;
        const int d0 = half * 256;
        for (int dm = d0; dm < d0 + 256; dm++) {
            float w = g_hwt[dm * 256 + ho];
            unsigned long long wp = pack2(w, w);
            #pragma unroll
            for (int ph = 0; ph < PH; ph++)
                fma2(acc2[ph], wp, zqu[dm * PH + ph]);
        }
        unsigned long long* ps = (unsigned long long*)zblk;
        if (half == 1) {
            #pragma unroll
            for (int ph = 0; ph < PH; ph++) ps[ho * PH + ph] = acc2[ph];
        }
        __syncthreads();
        if (half == 0) {
            int h = ho >> 6, o = ho & 63;
            float bb = hb[ho];
            #pragma unroll
            for (int ph = 0; ph < PH; ph++) {
                unsigned long long other = ps[ho * PH + ph];
                int p0 = 2 * ph, p1 = p0 + 1;
                float v0 = lo32(acc2[ph]) + lo32(other) + bb;
                float v1 = hi32(acc2[ph]) + hi32(other) + bb;
                out[OFF_BL + ((b * 4 + h) * TS + g * RP + p0) * 64 + o] = v0;
                out[OFF_BL + ((b * 4 + h) * TS + g * RP + p1) * 64 + o] = v1;
            }
        }
    }
}

// ---------------------------------------------------------------------------
extern "C" void kernel_launch(void* const* d_in, const int* in_sizes, int n_in,
                              void* d_out, int out_size)
{
    const float* audio = (const float*)d_in[0];
    const float* w1 = (const float*)d_in[1];
    const float* b1 = (const float*)d_in[2];
    const float* w2 = (const float*)d_in[3];
    const float* b2 = (const float*)d_in[4];
    const float* w3 = (const float*)d_in[5];
    const float* b3 = (const float*)d_in[6];
    const float* w4 = (const float*)d_in[7];
    const float* b4 = (const float*)d_in[8];
    const float* cb = (const float*)d_in[9];
    const float* hw = (const float*)d_in[10];
    const float* hb = (const float*)d_in[11];
    float* out = (float*)d_out;

    prep_conv1_kernel<<<1630, 256>>>(w2, w3, w4, hw, cb, audio, w1, b1, out);

    float* g_a1p; cudaGetSymbolAddress((void**)&g_a1p, g_a1);
    float* g_a2p; cudaGetSymbolAddress((void**)&g_a2p, g_a2);
    float* g_a3p; cudaGetSymbolAddress((void**)&g_a3p, g_a3);
    float* g_zpp; cudaGetSymbolAddress((void**)&g_zpp, g_zpart);
    float* g_w2tp; cudaGetSymbolAddress((void**)&g_w2tp, g_w2t);
    float* g_w3tp; cudaGetSymbolAddress((void**)&g_w3tp, g_w3t);
    float* g_w4tp; cudaGetSymbolAddress((void**)&g_w4tp, g_w4t);

    gemm_conv<320, 128, 8400, 7, 704, 64, 1, 1><<<dim3(132, 2), 256>>>(g_a1p, g_w2tp, b2, g_a2p);
    gemm_conv<640, 256, 3600, 3, 896, 128, 1, 1><<<dim3(57, 4), 256>>>(g_a2p, g_w3tp, b3, g_a3p);
    // conv4: K=768 split in 2 (KDIM=384), raw partials, y = spl*8 + ntile
    gemm_conv<384, 512, 1200, 1, 768, 0, 0, 2><<<dim3(19, 16), 256>>>(g_a3p, g_w4tp, b4, g_zpp);

    rvq_kernel<<<130, 512>>>(cb, b4, hb, out);
}